// round 10
// baseline (speedup 1.0000x reference)
#include <cuda_runtime.h>
#include <cuda_bf16.h>
#include <math.h>
#include <stdint.h>

#define HW 16384
#define IMG_W 128
#define DIM 192
#define HEADS 4
#define DHEAD 48
#define HIDDEN 510
#define BATCH 4

// ---------------- scratch (static device arrays) --------------------------------
__device__ __nv_bfloat16 g_S0b[BATCH * 1020 * HW]; // conv1x1 outputs (qkv:576 / pin:1020)
__device__ __nv_bfloat16 g_S1b[BATCH * 576 * HW];  // dw qkv out (576) / gated gdfn (512 pad)
__device__ __nv_bfloat16 g_S2b[BATCH * DIM * HW];  // LN-normalized xhat / attn output
__device__ __nv_bfloat16 g_Wqkv[640 * 192];        // padded 576->640
__device__ __nv_bfloat16 g_Wproj[256 * 192];       // padded 192->256
__device__ __nv_bfloat16 g_Wpin[1024 * 192];       // padded 1020->1024
__device__ __nv_bfloat16 g_Wpout[256 * 512];       // padded 192->256, K 510->512
__device__ float g_rnpart[64 * BATCH * 2 * DIM];   // [p][r]
__device__ float g_A[16 * DHEAD * DHEAD];
__device__ float g_Apart[16 * 16 * DHEAD * DHEAD];

// ---------------- helpers -------------------------------------------------------
__device__ __forceinline__ uint32_t pack_bf16(float x, float y) {
    __nv_bfloat162 h = __float22bfloat162_rn(make_float2(x, y));
    return *(uint32_t*)&h;
}
__device__ __forceinline__ uint32_t sm_addr(const void* p) {
    return (uint32_t)__cvta_generic_to_shared(p);
}
__device__ __forceinline__ void ldsm_x4(uint32_t* r, uint32_t addr) {
    asm volatile("ldmatrix.sync.aligned.m8n8.x4.shared.b16 {%0,%1,%2,%3}, [%4];"
        : "=r"(r[0]), "=r"(r[1]), "=r"(r[2]), "=r"(r[3]) : "r"(addr));
}
__device__ __forceinline__ void ldsm_x2t(uint32_t* r, uint32_t addr) {
    asm volatile("ldmatrix.sync.aligned.m8n8.x2.trans.shared.b16 {%0,%1}, [%2];"
        : "=r"(r[0]), "=r"(r[1]) : "r"(addr));
}
__device__ __forceinline__ void mma_bf16(float* d, const uint32_t* a, const uint32_t* b) {
    asm volatile("mma.sync.aligned.m16n8k16.row.col.f32.bf16.bf16.f32 "
        "{%0,%1,%2,%3}, {%4,%5,%6,%7}, {%8,%9}, {%0,%1,%2,%3};"
        : "+f"(d[0]), "+f"(d[1]), "+f"(d[2]), "+f"(d[3])
        : "r"(a[0]), "r"(a[1]), "r"(a[2]), "r"(a[3]), "r"(b[0]), "r"(b[1]));
}
__device__ __forceinline__ void cpa16(uint32_t dst, const void* src) {
    asm volatile("cp.async.cg.shared.global [%0], [%1], 16;" :: "r"(dst), "l"(src));
}
__device__ __forceinline__ void cpa_commit() { asm volatile("cp.async.commit_group;"); }
template<int N> __device__ __forceinline__ void cpa_wait() {
    asm volatile("cp.async.wait_group %0;" :: "n"(N));
}

// ---------------- weight fp32 -> bf16 with padding ------------------------------
__global__ __launch_bounds__(256) void wconv_kernel(const float* __restrict__ src,
                                                    __nv_bfloat16* __restrict__ dst,
                                                    int M, int K, int Mp, int Kp) {
    int idx = blockIdx.x * 256 + threadIdx.x;
    int tot = Mp * Kp;
    if (idx >= tot) return;
    int m = idx / Kp, k = idx - m * Kp;
    float v = (m < M && k < K) ? src[m * K + k] : 0.f;
    dst[idx] = __float2bfloat16(v);
}

// ---------------- LN: per-pixel stats + write normalized bf16 xhat ---------------
__global__ __launch_bounds__(256) void ln_apply_kernel(const float* __restrict__ x,
                                                       const float* __restrict__ lnW,
                                                       __nv_bfloat16* __restrict__ xh) {
    __shared__ float sw[DIM];
    int tid = threadIdx.x;
    if (tid < DIM) sw[tid] = lnW[tid];
    __syncthreads();
    int n = blockIdx.x * 256 + tid;
    int b = blockIdx.y;
    const float* xb = x + (long long)b * DIM * HW + n;
    float s = 0.f, s2 = 0.f;
#pragma unroll 8
    for (int c = 0; c < DIM; c++) {
        float v = xb[(long long)c * HW];
        s += v; s2 += v * v;
    }
    float m = s * (1.f / DIM);
    float var = s2 * (1.f / DIM) - m * m;
    float inv = rsqrtf(var + 1e-6f);
    __nv_bfloat16* ob = xh + (long long)b * DIM * HW + n;
#pragma unroll 8
    for (int c = 0; c < DIM; c++)
        ob[(long long)c * HW] = __float2bfloat16((xb[(long long)c * HW] - m) * inv * sw[c]);
}

// ---------------- bf16 GEMM v4: 3-stage cp.async pipeline ------------------------
// Out[b,m,n] = sum_k Wb[m,k]*X[k,n] (+Res). K mult of 32; Wb padded to 128-mult M.
// BM=128, BN=128, BK=32; 8 warps 2(M)x4(N), warp tile 64x32.
#define ASTRIDE 40
#define BSTRIDE 136
#define ABYTES (128 * ASTRIDE * 2)
#define BBYTES (32 * BSTRIDE * 2)
#define NSTAGE 3
#define GEMM_SMEM (NSTAGE * (ABYTES + BBYTES))

__global__ __launch_bounds__(256) void gemm_v4(const __nv_bfloat16* __restrict__ Wb,
                                               const __nv_bfloat16* __restrict__ X,
                                               void* __restrict__ Outv,
                                               const float* __restrict__ Res,
                                               int M, int K,
                                               long long xbs, long long obs,
                                               int outBf16, int addRes) {
    extern __shared__ __align__(16) uint8_t dynsm[];
    uint32_t aBase = sm_addr(dynsm);
    uint32_t bBase = aBase + NSTAGE * ABYTES;

    int tid = threadIdx.x;
    int lane = tid & 31, wid = tid >> 5;
    int wm = wid & 1, wn = wid >> 1;
    int ra = lane >> 2, ca = lane & 3;
    int n0 = blockIdx.x * 128;
    int m0 = blockIdx.y * 128;
    int b  = blockIdx.z;
    const __nv_bfloat16* Xb = X + (long long)b * xbs;

    // cp.async indices: A 128 rows x 4 chunks (2/thread), B 32 rows x 16 chunks (2/thread)
    int ar0 = tid >> 1, ac0 = (tid & 1) * 16;          // id = tid*2 .. : row=id>>2? use direct
    // A: id in [0,512): row=id>>2, chunk col=(id&3)*8
    // B: id in [0,512): row=id>>4, col=(id&15)*8

    float acc[4][4][4];
#pragma unroll
    for (int i = 0; i < 4; i++)
#pragma unroll
        for (int j = 0; j < 4; j++)
#pragma unroll
            for (int q = 0; q < 4; q++) acc[i][j][q] = 0.f;

    int nk = K >> 5;

    auto load_slab = [&](int kt, int s) {
        int kb = kt << 5;
        uint32_t aS = aBase + s * ABYTES;
        uint32_t bS = bBase + s * BBYTES;
#pragma unroll
        for (int i = 0; i < 2; i++) {
            int id = tid + i * 256;
            int m = id >> 2, kc = (id & 3) * 8;
            cpa16(aS + (uint32_t)(m * ASTRIDE + kc) * 2,
                  &Wb[(long long)(m0 + m) * K + kb + kc]);
        }
#pragma unroll
        for (int i = 0; i < 2; i++) {
            int id = tid + i * 256;
            int kr = id >> 4, nc = (id & 15) * 8;
            cpa16(bS + (uint32_t)(kr * BSTRIDE + nc) * 2,
                  &Xb[(long long)(kb + kr) * HW + n0 + nc]);
        }
    };

    // prologue: slabs 0,1
    load_slab(0, 0); cpa_commit();
    if (nk > 1) load_slab(1, 1);
    cpa_commit();

    for (int kt = 0; kt < nk; kt++) {
        cpa_wait<1>();
        __syncthreads();
        if (kt + 2 < nk) load_slab(kt + 2, (kt + 2) % NSTAGE);
        cpa_commit();
        int s = kt % NSTAGE;
        uint32_t aS = aBase + s * ABYTES;
        uint32_t bS = bBase + s * BBYTES;
#pragma unroll
        for (int ks = 0; ks < 2; ks++) {
            uint32_t afr[4][4], bfr[4][2];
#pragma unroll
            for (int tm = 0; tm < 4; tm++) {
                int m = wm * 64 + tm * 16 + (lane & 15);
                ldsm_x4(afr[tm], aS + (uint32_t)(m * ASTRIDE + ks * 16 + (lane >> 4) * 8) * 2);
            }
#pragma unroll
            for (int tn = 0; tn < 4; tn++) {
                int kr = ks * 16 + (lane & 15);
                ldsm_x2t(bfr[tn], bS + (uint32_t)(kr * BSTRIDE + wn * 32 + tn * 8) * 2);
            }
#pragma unroll
            for (int tm = 0; tm < 4; tm++)
#pragma unroll
                for (int tn = 0; tn < 4; tn++)
                    mma_bf16(acc[tm][tn], afr[tm], bfr[tn]);
        }
        __syncthreads();
    }

    if (outBf16) {
        __nv_bfloat16* Ob = (__nv_bfloat16*)Outv + (long long)b * obs;
#pragma unroll
        for (int tm = 0; tm < 4; tm++)
#pragma unroll
            for (int tn = 0; tn < 4; tn++) {
                int col = n0 + wn * 32 + tn * 8 + 2 * ca;
                int r0 = m0 + wm * 64 + tm * 16 + ra;
                int r1 = r0 + 8;
                if (r0 < M)
                    *(uint32_t*)&Ob[(long long)r0 * HW + col] =
                        pack_bf16(acc[tm][tn][0], acc[tm][tn][1]);
                if (r1 < M)
                    *(uint32_t*)&Ob[(long long)r1 * HW + col] =
                        pack_bf16(acc[tm][tn][2], acc[tm][tn][3]);
            }
    } else {
        float* Ob = (float*)Outv + (long long)b * obs;
        const float* Rb = Res + (long long)b * obs;
#pragma unroll
        for (int tm = 0; tm < 4; tm++)
#pragma unroll
            for (int tn = 0; tn < 4; tn++) {
                int col = n0 + wn * 32 + tn * 8 + 2 * ca;
                int r0 = m0 + wm * 64 + tm * 16 + ra;
                int r1 = r0 + 8;
                if (r0 < M) {
                    float2 v = make_float2(acc[tm][tn][0], acc[tm][tn][1]);
                    long long off = (long long)r0 * HW + col;
                    if (addRes) { float2 rr = *(const float2*)&Rb[off]; v.x += rr.x; v.y += rr.y; }
                    *(float2*)&Ob[off] = v;
                }
                if (r1 < M) {
                    float2 v = make_float2(acc[tm][tn][2], acc[tm][tn][3]);
                    long long off = (long long)r1 * HW + col;
                    if (addRes) { float2 rr = *(const float2*)&Rb[off]; v.x += rr.x; v.y += rr.y; }
                    *(float2*)&Ob[off] = v;
                }
            }
    }
}

// ---------------- depthwise 3x3 qkv (bf16 io) + q/k sumsq partials --------------
__global__ __launch_bounds__(256) void dw_qkv_kernel(const __nv_bfloat16* __restrict__ in,
                                                     const float* __restrict__ w9,
                                                     __nv_bfloat16* __restrict__ out) {
    int c = blockIdx.y, b = blockIdx.z;
    long long base = ((long long)b * 576 + c) * HW;
    const __nv_bfloat16* ib = in + base;
    float w[9];
#pragma unroll
    for (int i = 0; i < 9; i++) w[i] = w9[c * 9 + i];
    int n = blockIdx.x * 256 + threadIdx.x;
    int y = n >> 7, x = n & 127;
    float s = 0.f;
#pragma unroll
    for (int ky = 0; ky < 3; ky++) {
        int iy = y + ky - 1;
        if ((unsigned)iy >= IMG_W) continue;
#pragma unroll
        for (int kx = 0; kx < 3; kx++) {
            int ix = x + kx - 1;
            if ((unsigned)ix >= IMG_W) continue;
            s += w[ky * 3 + kx] * __bfloat162float(ib[iy * IMG_W + ix]);
        }
    }
    out[base + n] = __float2bfloat16(s);
    if (c < 384) {
        __shared__ float red[256];
        red[threadIdx.x] = s * s;
        __syncthreads();
        for (int st = 128; st; st >>= 1) {
            if (threadIdx.x < st) red[threadIdx.x] += red[threadIdx.x + st];
            __syncthreads();
        }
        if (threadIdx.x == 0)
            g_rnpart[(long long)blockIdx.x * (BATCH * 384) + b * 384 + c] = red[0];
    }
}

// ---------------- split-K partial Q.K^T (bf16 in) -------------------------------
__global__ __launch_bounds__(256) void attn_part_kernel() {
    int chunk = blockIdx.x;
    int bh = blockIdx.y;
    int b = bh >> 2, h = bh & 3;
    const __nv_bfloat16* qb = g_S1b + ((long long)b * 576 + h * DHEAD) * HW;
    const __nv_bfloat16* kb = g_S1b + ((long long)b * 576 + DIM + h * DHEAD) * HW;
    __shared__ float sq[48][65], sk[48][65];
    int tid = threadIdx.x;
    int tc = tid & 15, tr = tid >> 4;
    int c0 = tr * 3, d0 = tc * 3;
    float acc[3][3] = {};
    long long nbase = (long long)chunk * 1024;
    for (int nn = 0; nn < 1024; nn += 64) {
#pragma unroll
        for (int i = 0; i < 6; i++) {
            int idx = tid + i * 256;
            int r = idx >> 5, cp = (idx & 31) * 2;
            __nv_bfloat162 q2 = *(const __nv_bfloat162*)&qb[(long long)r * HW + nbase + nn + cp];
            __nv_bfloat162 k2 = *(const __nv_bfloat162*)&kb[(long long)r * HW + nbase + nn + cp];
            sq[r][cp] = __bfloat162float(q2.x); sq[r][cp + 1] = __bfloat162float(q2.y);
            sk[r][cp] = __bfloat162float(k2.x); sk[r][cp + 1] = __bfloat162float(k2.y);
        }
        __syncthreads();
#pragma unroll
        for (int kk = 0; kk < 64; kk++) {
            float q0 = sq[c0][kk], q1 = sq[c0 + 1][kk], q2 = sq[c0 + 2][kk];
            float k0 = sk[d0][kk], k1 = sk[d0 + 1][kk], k2 = sk[d0 + 2][kk];
            acc[0][0] += q0 * k0; acc[0][1] += q0 * k1; acc[0][2] += q0 * k2;
            acc[1][0] += q1 * k0; acc[1][1] += q1 * k1; acc[1][2] += q1 * k2;
            acc[2][0] += q2 * k0; acc[2][1] += q2 * k1; acc[2][2] += q2 * k2;
        }
        __syncthreads();
    }
    float* P = g_Apart + ((long long)bh * 16 + chunk) * (DHEAD * DHEAD);
#pragma unroll
    for (int i = 0; i < 3; i++)
#pragma unroll
        for (int j = 0; j < 3; j++)
            P[(c0 + i) * DHEAD + d0 + j] = acc[i][j];
}

// ---------------- reduce partials + rownorms, scale, softmax --------------------
__global__ __launch_bounds__(256) void attn_finish_kernel(const float* __restrict__ temp) {
    int bh = blockIdx.x;
    int b = bh >> 2, h = bh & 3;
    __shared__ float sA[DHEAD * DHEAD];
    __shared__ float srn_q[DHEAD], srn_k[DHEAD];
    int tid = threadIdx.x;
    if (tid < 96) {
        int i = tid;
        int isK = (i >= DHEAD);
        int cc = i - isK * DHEAD;
        int row = b * 384 + isK * DIM + h * DHEAD + cc;
        float s = 0.f;
#pragma unroll 8
        for (int p = 0; p < 64; p++) s += g_rnpart[(long long)p * (BATCH * 384) + row];
        float v = 1.f / fmaxf(sqrtf(s), 1e-12f);
        if (isK) srn_k[cc] = v; else srn_q[cc] = v;
    }
    __syncthreads();
    for (int i = tid; i < DHEAD * DHEAD; i += 256) {
        float s = 0.f;
        for (int p = 0; p < 16; p++)
            s += g_Apart[((long long)bh * 16 + p) * (DHEAD * DHEAD) + i];
        int c = i / DHEAD, d = i % DHEAD;
        sA[i] = s * srn_q[c] * srn_k[d] * temp[h];
    }
    __syncthreads();
    if (tid < DHEAD) {
        float mx = -1e30f;
        for (int d = 0; d < DHEAD; d++) mx = fmaxf(mx, sA[tid * DHEAD + d]);
        float sum = 0.f;
        for (int d = 0; d < DHEAD; d++) sum += __expf(sA[tid * DHEAD + d] - mx);
        float inv = 1.f / sum;
        for (int d = 0; d < DHEAD; d++)
            g_A[bh * DHEAD * DHEAD + tid * DHEAD + d] =
                __expf(sA[tid * DHEAD + d] - mx) * inv;
    }
}

// ---------------- out = A @ V (bf16 io) -----------------------------------------
__global__ __launch_bounds__(256) void av_kernel() {
    int bh = blockIdx.y;
    int b = bh >> 2, h = bh & 3;
    __shared__ float sA[DHEAD][DHEAD];
    int tid = threadIdx.x;
    for (int i = tid; i < DHEAD * DHEAD; i += 256)
        sA[i / DHEAD][i % DHEAD] = g_A[bh * DHEAD * DHEAD + i];
    __syncthreads();
    int n = blockIdx.x * 256 + tid;
    const __nv_bfloat16* vb = g_S1b + ((long long)b * 576 + 2 * DIM + h * DHEAD) * HW + n;
    float v[DHEAD];
#pragma unroll
    for (int d = 0; d < DHEAD; d++) v[d] = __bfloat162float(vb[(long long)d * HW]);
    __nv_bfloat16* ob = g_S2b + ((long long)b * DIM + h * DHEAD) * HW + n;
#pragma unroll 4
    for (int c = 0; c < DHEAD; c++) {
        float s = 0.f;
#pragma unroll
        for (int d = 0; d < DHEAD; d++) s += sA[c][d] * v[d];
        ob[(long long)c * HW] = __float2bfloat16(s);
    }
}

// ---------------- fused GDFN depthwise 3x3 + GELU gate (bf16 io, 512-pad out) ---
__global__ __launch_bounds__(256) void dw_gate_kernel(const __nv_bfloat16* __restrict__ in,
                                                      const float* __restrict__ w9,
                                                      __nv_bfloat16* __restrict__ out) {
    int c = blockIdx.y, b = blockIdx.z;
    int n = blockIdx.x * 256 + threadIdx.x;
    if (c >= HIDDEN) {
        out[((long long)b * 512 + c) * HW + n] = __float2bfloat16(0.f);
        return;
    }
    const __nv_bfloat16* ib1 = in + ((long long)b * 1020 + c) * HW;
    const __nv_bfloat16* ib2 = in + ((long long)b * 1020 + HIDDEN + c) * HW;
    float w1[9], w2[9];
#pragma unroll
    for (int i = 0; i < 9; i++) { w1[i] = w9[c * 9 + i]; w2[i] = w9[(HIDDEN + c) * 9 + i]; }
    int y = n >> 7, x = n & 127;
    float s1 = 0.f, s2 = 0.f;
#pragma unroll
    for (int ky = 0; ky < 3; ky++) {
        int iy = y + ky - 1;
        if ((unsigned)iy >= IMG_W) continue;
#pragma unroll
        for (int kx = 0; kx < 3; kx++) {
            int ix = x + kx - 1;
            if ((unsigned)ix >= IMG_W) continue;
            s1 += w1[ky * 3 + kx] * __bfloat162float(ib1[iy * IMG_W + ix]);
            s2 += w2[ky * 3 + kx] * __bfloat162float(ib2[iy * IMG_W + ix]);
        }
    }
    float g = 0.5f * s1 * (1.f + erff(s1 * 0.70710678118654752f));
    out[((long long)b * 512 + c) * HW + n] = __float2bfloat16(g * s2);
}

// =============================================================================
extern "C" void kernel_launch(void* const* d_in, const int* in_sizes, int n_in,
                              void* d_out, int out_size) {
    const float* x     = (const float*)d_in[0];
    const float* n1w   = (const float*)d_in[1];
    const float* qkvw  = (const float*)d_in[2];
    const float* qkvdw = (const float*)d_in[3];
    const float* temp  = (const float*)d_in[4];
    const float* projw = (const float*)d_in[5];
    const float* n2w   = (const float*)d_in[6];
    const float* pinw  = (const float*)d_in[7];
    const float* dww   = (const float*)d_in[8];
    const float* poutw = (const float*)d_in[9];
    float* out = (float*)d_out;

    __nv_bfloat16 *S0b, *S1b, *S2b, *Wqkv, *Wproj, *Wpin, *Wpout;
    cudaGetSymbolAddress((void**)&S0b, g_S0b);
    cudaGetSymbolAddress((void**)&S1b, g_S1b);
    cudaGetSymbolAddress((void**)&S2b, g_S2b);
    cudaGetSymbolAddress((void**)&Wqkv, g_Wqkv);
    cudaGetSymbolAddress((void**)&Wproj, g_Wproj);
    cudaGetSymbolAddress((void**)&Wpin, g_Wpin);
    cudaGetSymbolAddress((void**)&Wpout, g_Wpout);

    static int s_attr_done = 0;
    if (!s_attr_done) {
        cudaFuncSetAttribute(gemm_v4, cudaFuncAttributeMaxDynamicSharedMemorySize, GEMM_SMEM);
        s_attr_done = 1;
    }

    dim3 pxGrid(HW / 256, BATCH);

    // weight conversions first (keeps qkv GEMM at a stable ncu skip offset)
    wconv_kernel<<<(640 * 192 + 255) / 256, 256>>>(qkvw, Wqkv, 576, 192, 640, 192);
    wconv_kernel<<<(256 * 192 + 255) / 256, 256>>>(projw, Wproj, 192, 192, 256, 192);
    wconv_kernel<<<(1024 * 192 + 255) / 256, 256>>>(pinw, Wpin, 1020, 192, 1024, 192);
    wconv_kernel<<<(256 * 512 + 255) / 256, 256>>>(poutw, Wpout, 192, 510, 256, 512);

    // ---- MDTA branch ----
    ln_apply_kernel<<<pxGrid, 256>>>(x, n1w, S2b);

    // qkv 1x1: 576x192 (padded 640)
    gemm_v4<<<dim3(HW / 128, 5, BATCH), 256, GEMM_SMEM>>>(
        Wqkv, S2b, S0b, nullptr, 576, 192, (long long)DIM * HW, (long long)576 * HW, 1, 0);

    dw_qkv_kernel<<<dim3(HW / 256, 576, BATCH), 256>>>(S0b, qkvdw, S1b);
    attn_part_kernel<<<dim3(16, 16), 256>>>();
    attn_finish_kernel<<<16, 256>>>(temp);
    av_kernel<<<dim3(HW / 256, 16), 256>>>();

    // proj 1x1 (192x192, padded 256): bf16 -> fp32 + residual(x)
    gemm_v4<<<dim3(HW / 128, 2, BATCH), 256, GEMM_SMEM>>>(
        Wproj, S2b, out, x, 192, 192, (long long)DIM * HW, (long long)DIM * HW, 0, 1);

    // ---- GDFN branch ----
    ln_apply_kernel<<<pxGrid, 256>>>(out, n2w, S2b);

    // pin 1x1 (1020x192 padded 1024)
    gemm_v4<<<dim3(HW / 128, 8, BATCH), 256, GEMM_SMEM>>>(
        Wpin, S2b, S0b, nullptr, 1020, 192, (long long)DIM * HW, (long long)1020 * HW, 1, 0);

    dw_gate_kernel<<<dim3(HW / 256, 512, BATCH), 256>>>(S0b, dww, S1b);

    // pout 1x1 (192x512 padded 256): bf16 -> fp32 + residual(d_out)
    gemm_v4<<<dim3(HW / 128, 2, BATCH), 256, GEMM_SMEM>>>(
        Wpout, S1b, out, out, 192, 512, (long long)512 * HW, (long long)DIM * HW, 0, 1);
}

// round 11
// speedup vs baseline: 1.3700x; 1.3700x over previous
#include <cuda_runtime.h>
#include <cuda_bf16.h>
#include <math.h>
#include <stdint.h>

#define HW 16384
#define IMG_W 128
#define DIM 192
#define HEADS 4
#define DHEAD 48
#define HIDDEN 510
#define BATCH 4
#define NPART 8

// ---------------- scratch (static device arrays) --------------------------------
__device__ __nv_bfloat16 g_S0b[BATCH * 1020 * HW]; // conv1x1 outputs (qkv:576 / pin:1020)
__device__ __nv_bfloat16 g_S1b[BATCH * 576 * HW];  // dw qkv out (576) / gated gdfn (512 pad)
__device__ __nv_bfloat16 g_S2b[BATCH * DIM * HW];  // LN-normalized xhat / attn output
__device__ __nv_bfloat16 g_Wqkv[576 * 192];
__device__ __nv_bfloat16 g_Wproj[192 * 192];
__device__ __nv_bfloat16 g_Wpin[1024 * 192];       // padded 1020->1024
__device__ __nv_bfloat16 g_Wpout[192 * 512];       // padded K 510->512
__device__ float g_rnpart[NPART * BATCH * 2 * DIM]; // [p][r]
__device__ float g_A[16 * DHEAD * DHEAD];
__device__ float g_Apart[16 * 16 * DHEAD * DHEAD];

// ---------------- helpers -------------------------------------------------------
__device__ __forceinline__ uint32_t pack_bf16(float x, float y) {
    __nv_bfloat162 h = __float22bfloat162_rn(make_float2(x, y));
    return *(uint32_t*)&h;
}
__device__ __forceinline__ uint32_t sm_addr(const void* p) {
    return (uint32_t)__cvta_generic_to_shared(p);
}
__device__ __forceinline__ void ldsm_x4(uint32_t* r, uint32_t addr) {
    asm volatile("ldmatrix.sync.aligned.m8n8.x4.shared.b16 {%0,%1,%2,%3}, [%4];"
        : "=r"(r[0]), "=r"(r[1]), "=r"(r[2]), "=r"(r[3]) : "r"(addr));
}
__device__ __forceinline__ void ldsm_x2t(uint32_t* r, uint32_t addr) {
    asm volatile("ldmatrix.sync.aligned.m8n8.x2.trans.shared.b16 {%0,%1}, [%2];"
        : "=r"(r[0]), "=r"(r[1]) : "r"(addr));
}
__device__ __forceinline__ void mma_bf16(float* d, const uint32_t* a, const uint32_t* b) {
    asm volatile("mma.sync.aligned.m16n8k16.row.col.f32.bf16.bf16.f32 "
        "{%0,%1,%2,%3}, {%4,%5,%6,%7}, {%8,%9}, {%0,%1,%2,%3};"
        : "+f"(d[0]), "+f"(d[1]), "+f"(d[2]), "+f"(d[3])
        : "r"(a[0]), "r"(a[1]), "r"(a[2]), "r"(a[3]), "r"(b[0]), "r"(b[1]));
}
__device__ __forceinline__ void cpa16(uint32_t dst, const void* src) {
    asm volatile("cp.async.cg.shared.global [%0], [%1], 16;" :: "r"(dst), "l"(src));
}
__device__ __forceinline__ void cpa_commit() { asm volatile("cp.async.commit_group;"); }
template<int N> __device__ __forceinline__ void cpa_wait() {
    asm volatile("cp.async.wait_group %0;" :: "n"(N));
}

// ---------------- weight fp32 -> bf16 with padding ------------------------------
__global__ __launch_bounds__(256) void wconv_kernel(const float* __restrict__ src,
                                                    __nv_bfloat16* __restrict__ dst,
                                                    int M, int K, int Mp, int Kp) {
    int idx = blockIdx.x * 256 + threadIdx.x;
    int tot = Mp * Kp;
    if (idx >= tot) return;
    int m = idx / Kp, k = idx - m * Kp;
    float v = (m < M && k < K) ? src[m * K + k] : 0.f;
    dst[idx] = __float2bfloat16(v);
}

// ---------------- LN: per-pixel stats + write normalized bf16 xhat ---------------
__global__ __launch_bounds__(256) void ln_apply_kernel(const float* __restrict__ x,
                                                       const float* __restrict__ lnW,
                                                       __nv_bfloat16* __restrict__ xh) {
    __shared__ float sw[DIM];
    int tid = threadIdx.x;
    if (tid < DIM) sw[tid] = lnW[tid];
    __syncthreads();
    int n = blockIdx.x * 256 + tid;
    int b = blockIdx.y;
    const float* xb = x + (long long)b * DIM * HW + n;
    float s = 0.f, s2 = 0.f;
#pragma unroll 8
    for (int c = 0; c < DIM; c++) {
        float v = xb[(long long)c * HW];
        s += v; s2 += v * v;
    }
    float m = s * (1.f / DIM);
    float var = s2 * (1.f / DIM) - m * m;
    float inv = rsqrtf(var + 1e-6f);
    __nv_bfloat16* ob = xh + (long long)b * DIM * HW + n;
#pragma unroll 8
    for (int c = 0; c < DIM; c++)
        ob[(long long)c * HW] = __float2bfloat16((xb[(long long)c * HW] - m) * inv * sw[c]);
}

// ---------------- bf16 GEMM (v3, 2-stage cp.async, BM64/BN256/BK32) -------------
__global__ __launch_bounds__(256) void gemm_pipe(const __nv_bfloat16* __restrict__ Wb,
                                                 const __nv_bfloat16* __restrict__ X,
                                                 void* __restrict__ Outv,
                                                 const float* __restrict__ Res,
                                                 int M, int K,
                                                 long long xbs, long long obs,
                                                 int outBf16, int addRes) {
    __shared__ __align__(16) __nv_bfloat16 As[2][64][40];
    __shared__ __align__(16) __nv_bfloat16 Bs[2][32][264];
    int tid = threadIdx.x;
    int lane = tid & 31, wn = tid >> 5;
    int ra = lane >> 2, ca = lane & 3;
    int n0 = blockIdx.x * 256;
    int m0 = blockIdx.y * 64;
    int b  = blockIdx.z;
    const __nv_bfloat16* Xb = X + (long long)b * xbs;

    int ar = tid >> 2, ac = (tid & 3) * 8;

    float acc[4][4][4];
#pragma unroll
    for (int i = 0; i < 4; i++)
#pragma unroll
        for (int j = 0; j < 4; j++)
#pragma unroll
            for (int q = 0; q < 4; q++) acc[i][j][q] = 0.f;

    int nk = K >> 5;

    cpa16(sm_addr(&As[0][ar][ac]), &Wb[(long long)(m0 + ar) * K + ac]);
#pragma unroll
    for (int i = 0; i < 4; i++) {
        int chunk = tid + i * 256;
        int brow = chunk >> 5, bcol = (chunk & 31) * 8;
        cpa16(sm_addr(&Bs[0][brow][bcol]), &Xb[(long long)brow * HW + n0 + bcol]);
    }
    cpa_commit();

    for (int kt = 0; kt < nk; kt++) {
        if (kt + 1 < nk) {
            int s = (kt + 1) & 1;
            int k0 = (kt + 1) << 5;
            cpa16(sm_addr(&As[s][ar][ac]), &Wb[(long long)(m0 + ar) * K + k0 + ac]);
#pragma unroll
            for (int i = 0; i < 4; i++) {
                int chunk = tid + i * 256;
                int brow = chunk >> 5, bcol = (chunk & 31) * 8;
                cpa16(sm_addr(&Bs[s][brow][bcol]), &Xb[(long long)(k0 + brow) * HW + n0 + bcol]);
            }
        }
        cpa_commit();
        cpa_wait<1>();
        __syncthreads();
        int s = kt & 1;
#pragma unroll
        for (int ks = 0; ks < 2; ks++) {
            uint32_t afr[4][4], bfr[4][2];
#pragma unroll
            for (int tm = 0; tm < 4; tm++)
                ldsm_x4(afr[tm],
                    sm_addr(&As[s][tm * 16 + (lane & 15)][ks * 16 + (lane >> 4) * 8]));
#pragma unroll
            for (int tn = 0; tn < 4; tn++)
                ldsm_x2t(bfr[tn],
                    sm_addr(&Bs[s][ks * 16 + (lane & 15)][wn * 32 + tn * 8]));
#pragma unroll
            for (int tm = 0; tm < 4; tm++)
#pragma unroll
                for (int tn = 0; tn < 4; tn++)
                    mma_bf16(acc[tm][tn], afr[tm], bfr[tn]);
        }
        __syncthreads();
    }

    if (outBf16) {
        __nv_bfloat16* Ob = (__nv_bfloat16*)Outv + (long long)b * obs;
#pragma unroll
        for (int tm = 0; tm < 4; tm++)
#pragma unroll
            for (int tn = 0; tn < 4; tn++) {
                int col = n0 + wn * 32 + tn * 8 + 2 * ca;
                int r0 = m0 + tm * 16 + ra;
                int r1 = r0 + 8;
                if (r0 < M)
                    *(uint32_t*)&Ob[(long long)r0 * HW + col] =
                        pack_bf16(acc[tm][tn][0], acc[tm][tn][1]);
                if (r1 < M)
                    *(uint32_t*)&Ob[(long long)r1 * HW + col] =
                        pack_bf16(acc[tm][tn][2], acc[tm][tn][3]);
            }
    } else {
        float* Ob = (float*)Outv + (long long)b * obs;
        const float* Rb = Res + (long long)b * obs;
#pragma unroll
        for (int tm = 0; tm < 4; tm++)
#pragma unroll
            for (int tn = 0; tn < 4; tn++) {
                int col = n0 + wn * 32 + tn * 8 + 2 * ca;
                int r0 = m0 + tm * 16 + ra;
                int r1 = r0 + 8;
                if (r0 < M) {
                    float2 v = make_float2(acc[tm][tn][0], acc[tm][tn][1]);
                    long long off = (long long)r0 * HW + col;
                    if (addRes) { float2 rr = *(const float2*)&Rb[off]; v.x += rr.x; v.y += rr.y; }
                    *(float2*)&Ob[off] = v;
                }
                if (r1 < M) {
                    float2 v = make_float2(acc[tm][tn][2], acc[tm][tn][3]);
                    long long off = (long long)r1 * HW + col;
                    if (addRes) { float2 rr = *(const float2*)&Rb[off]; v.x += rr.x; v.y += rr.y; }
                    *(float2*)&Ob[off] = v;
                }
            }
    }
}

// ---------------- depthwise 3x3 qkv: vectorized 16-row tiles --------------------
// grid (8, 576, BATCH); each thread computes 8 consecutive pixels.
__global__ __launch_bounds__(256) void dw_qkv_kernel(const __nv_bfloat16* __restrict__ in,
                                                     const float* __restrict__ w9,
                                                     __nv_bfloat16* __restrict__ out) {
    __shared__ __nv_bfloat16 st[18][136];
    __shared__ float red[256];
    int c = blockIdx.y, b = blockIdx.z;
    long long base = ((long long)b * 576 + c) * HW;
    int y0 = blockIdx.x * 16;
    int tid = threadIdx.x;
    float w[9];
#pragma unroll
    for (int i = 0; i < 9; i++) w[i] = w9[c * 9 + i];

    for (int id = tid; id < 288; id += 256) {
        int r = id >> 4, c8 = (id & 15) * 8;
        int gy = y0 - 1 + r;
        uint4 v = make_uint4(0u, 0u, 0u, 0u);
        if ((unsigned)gy < IMG_W) v = *(const uint4*)&in[base + gy * IMG_W + c8];
        *(uint4*)&st[r][c8] = v;
    }
    __syncthreads();

    int r = tid >> 4, x0 = (tid & 15) * 8;
    float o[8] = {};
#pragma unroll
    for (int ky = 0; ky < 3; ky++) {
        float t[10];
#pragma unroll
        for (int i = 0; i < 10; i++) {
            int xx = x0 - 1 + i;
            t[i] = ((unsigned)xx < IMG_W) ? __bfloat162float(st[r + ky][xx]) : 0.f;
        }
        float w0 = w[ky * 3], w1 = w[ky * 3 + 1], w2 = w[ky * 3 + 2];
#pragma unroll
        for (int j = 0; j < 8; j++)
            o[j] += w0 * t[j] + w1 * t[j + 1] + w2 * t[j + 2];
    }
    uint4 pv;
    uint32_t* pp = (uint32_t*)&pv;
#pragma unroll
    for (int i = 0; i < 4; i++) pp[i] = pack_bf16(o[2 * i], o[2 * i + 1]);
    *(uint4*)&out[base + (y0 + r) * IMG_W + x0] = pv;

    if (c < 384) {
        float ss = 0.f;
#pragma unroll
        for (int j = 0; j < 8; j++) ss += o[j] * o[j];
        red[tid] = ss;
        __syncthreads();
        for (int stp = 128; stp; stp >>= 1) {
            if (tid < stp) red[tid] += red[tid + stp];
            __syncthreads();
        }
        if (tid == 0)
            g_rnpart[(long long)blockIdx.x * (BATCH * 384) + b * 384 + c] = red[0];
    }
}

// ---------------- split-K partial Q.K^T (bf16 in) -------------------------------
__global__ __launch_bounds__(256) void attn_part_kernel() {
    int chunk = blockIdx.x;
    int bh = blockIdx.y;
    int b = bh >> 2, h = bh & 3;
    const __nv_bfloat16* qb = g_S1b + ((long long)b * 576 + h * DHEAD) * HW;
    const __nv_bfloat16* kb = g_S1b + ((long long)b * 576 + DIM + h * DHEAD) * HW;
    __shared__ float sq[48][65], sk[48][65];
    int tid = threadIdx.x;
    int tc = tid & 15, tr = tid >> 4;
    int c0 = tr * 3, d0 = tc * 3;
    float acc[3][3] = {};
    long long nbase = (long long)chunk * 1024;
    for (int nn = 0; nn < 1024; nn += 64) {
#pragma unroll
        for (int i = 0; i < 6; i++) {
            int idx = tid + i * 256;
            int r = idx >> 5, cp = (idx & 31) * 2;
            __nv_bfloat162 q2 = *(const __nv_bfloat162*)&qb[(long long)r * HW + nbase + nn + cp];
            __nv_bfloat162 k2 = *(const __nv_bfloat162*)&kb[(long long)r * HW + nbase + nn + cp];
            sq[r][cp] = __bfloat162float(q2.x); sq[r][cp + 1] = __bfloat162float(q2.y);
            sk[r][cp] = __bfloat162float(k2.x); sk[r][cp + 1] = __bfloat162float(k2.y);
        }
        __syncthreads();
#pragma unroll
        for (int kk = 0; kk < 64; kk++) {
            float q0 = sq[c0][kk], q1 = sq[c0 + 1][kk], q2 = sq[c0 + 2][kk];
            float k0 = sk[d0][kk], k1 = sk[d0 + 1][kk], k2 = sk[d0 + 2][kk];
            acc[0][0] += q0 * k0; acc[0][1] += q0 * k1; acc[0][2] += q0 * k2;
            acc[1][0] += q1 * k0; acc[1][1] += q1 * k1; acc[1][2] += q1 * k2;
            acc[2][0] += q2 * k0; acc[2][1] += q2 * k1; acc[2][2] += q2 * k2;
        }
        __syncthreads();
    }
    float* P = g_Apart + ((long long)bh * 16 + chunk) * (DHEAD * DHEAD);
#pragma unroll
    for (int i = 0; i < 3; i++)
#pragma unroll
        for (int j = 0; j < 3; j++)
            P[(c0 + i) * DHEAD + d0 + j] = acc[i][j];
}

// ---------------- reduce partials + rownorms, scale, softmax --------------------
__global__ __launch_bounds__(256) void attn_finish_kernel(const float* __restrict__ temp) {
    int bh = blockIdx.x;
    int b = bh >> 2, h = bh & 3;
    __shared__ float sA[DHEAD * DHEAD];
    __shared__ float srn_q[DHEAD], srn_k[DHEAD];
    int tid = threadIdx.x;
    if (tid < 96) {
        int i = tid;
        int isK = (i >= DHEAD);
        int cc = i - isK * DHEAD;
        int row = b * 384 + isK * DIM + h * DHEAD + cc;
        float s = 0.f;
#pragma unroll
        for (int p = 0; p < NPART; p++) s += g_rnpart[(long long)p * (BATCH * 384) + row];
        float v = 1.f / fmaxf(sqrtf(s), 1e-12f);
        if (isK) srn_k[cc] = v; else srn_q[cc] = v;
    }
    __syncthreads();
    for (int i = tid; i < DHEAD * DHEAD; i += 256) {
        float s = 0.f;
        for (int p = 0; p < 16; p++)
            s += g_Apart[((long long)bh * 16 + p) * (DHEAD * DHEAD) + i];
        int c = i / DHEAD, d = i % DHEAD;
        sA[i] = s * srn_q[c] * srn_k[d] * temp[h];
    }
    __syncthreads();
    if (tid < DHEAD) {
        float mx = -1e30f;
        for (int d = 0; d < DHEAD; d++) mx = fmaxf(mx, sA[tid * DHEAD + d]);
        float sum = 0.f;
        for (int d = 0; d < DHEAD; d++) sum += __expf(sA[tid * DHEAD + d] - mx);
        float inv = 1.f / sum;
        for (int d = 0; d < DHEAD; d++)
            g_A[bh * DHEAD * DHEAD + tid * DHEAD + d] =
                __expf(sA[tid * DHEAD + d] - mx) * inv;
    }
}

// ---------------- out = A @ V (bf16 io, 2 px/thread) ----------------------------
__global__ __launch_bounds__(256) void av_kernel() {
    int bh = blockIdx.y;
    int b = bh >> 2, h = bh & 3;
    __shared__ float sA[DHEAD][DHEAD];
    int tid = threadIdx.x;
    for (int i = tid; i < DHEAD * DHEAD; i += 256)
        sA[i / DHEAD][i % DHEAD] = g_A[bh * DHEAD * DHEAD + i];
    __syncthreads();
    int n2 = (blockIdx.x * 256 + tid) * 2;
    const __nv_bfloat16* vb = g_S1b + ((long long)b * 576 + 2 * DIM + h * DHEAD) * HW + n2;
    float2 v[DHEAD];
#pragma unroll
    for (int d = 0; d < DHEAD; d++) {
        __nv_bfloat162 p = *(const __nv_bfloat162*)&vb[(long long)d * HW];
        v[d] = make_float2(__bfloat162float(p.x), __bfloat162float(p.y));
    }
    __nv_bfloat16* ob = g_S2b + ((long long)b * DIM + h * DHEAD) * HW + n2;
#pragma unroll 4
    for (int c = 0; c < DHEAD; c++) {
        float sx = 0.f, sy = 0.f;
#pragma unroll
        for (int d = 0; d < DHEAD; d++) {
            float a = sA[c][d];
            sx += a * v[d].x; sy += a * v[d].y;
        }
        *(uint32_t*)&ob[(long long)c * HW] = pack_bf16(sx, sy);
    }
}

// ---------------- fused GDFN dw3x3 + GELU gate: vectorized 16-row tiles ---------
// grid (8, 512, BATCH); each thread computes 8 consecutive pixels.
__global__ __launch_bounds__(256) void dw_gate_kernel(const __nv_bfloat16* __restrict__ in,
                                                      const float* __restrict__ w9,
                                                      __nv_bfloat16* __restrict__ out) {
    __shared__ __nv_bfloat16 st1[18][136], st2[18][136];
    int c = blockIdx.y, b = blockIdx.z;
    int y0 = blockIdx.x * 16;
    int tid = threadIdx.x;
    int r = tid >> 4, x0 = (tid & 15) * 8;
    long long obase = ((long long)b * 512 + c) * HW;

    if (c >= HIDDEN) {   // pad channels -> zero
        uint4 z = make_uint4(0u, 0u, 0u, 0u);
        *(uint4*)&out[obase + (y0 + r) * IMG_W + x0] = z;
        return;
    }
    long long base1 = ((long long)b * 1020 + c) * HW;
    long long base2 = ((long long)b * 1020 + HIDDEN + c) * HW;
    float w1[9], w2[9];
#pragma unroll
    for (int i = 0; i < 9; i++) { w1[i] = w9[c * 9 + i]; w2[i] = w9[(HIDDEN + c) * 9 + i]; }

    for (int id = tid; id < 288; id += 256) {
        int rr = id >> 4, c8 = (id & 15) * 8;
        int gy = y0 - 1 + rr;
        uint4 v1 = make_uint4(0u, 0u, 0u, 0u), v2 = v1;
        if ((unsigned)gy < IMG_W) {
            v1 = *(const uint4*)&in[base1 + gy * IMG_W + c8];
            v2 = *(const uint4*)&in[base2 + gy * IMG_W + c8];
        }
        *(uint4*)&st1[rr][c8] = v1;
        *(uint4*)&st2[rr][c8] = v2;
    }
    __syncthreads();

    float o1[8] = {}, o2[8] = {};
#pragma unroll
    for (int ky = 0; ky < 3; ky++) {
        float t1[10], t2[10];
#pragma unroll
        for (int i = 0; i < 10; i++) {
            int xx = x0 - 1 + i;
            bool ok = (unsigned)xx < IMG_W;
            t1[i] = ok ? __bfloat162float(st1[r + ky][xx]) : 0.f;
            t2[i] = ok ? __bfloat162float(st2[r + ky][xx]) : 0.f;
        }
        float a0 = w1[ky * 3], a1 = w1[ky * 3 + 1], a2 = w1[ky * 3 + 2];
        float b0 = w2[ky * 3], b1 = w2[ky * 3 + 1], b2 = w2[ky * 3 + 2];
#pragma unroll
        for (int j = 0; j < 8; j++) {
            o1[j] += a0 * t1[j] + a1 * t1[j + 1] + a2 * t1[j + 2];
            o2[j] += b0 * t2[j] + b1 * t2[j + 1] + b2 * t2[j + 2];
        }
    }
    uint4 pv;
    uint32_t* pp = (uint32_t*)&pv;
#pragma unroll
    for (int i = 0; i < 4; i++) {
        float g0 = 0.5f * o1[2 * i] * (1.f + erff(o1[2 * i] * 0.70710678118654752f));
        float g1 = 0.5f * o1[2 * i + 1] * (1.f + erff(o1[2 * i + 1] * 0.70710678118654752f));
        pp[i] = pack_bf16(g0 * o2[2 * i], g1 * o2[2 * i + 1]);
    }
    *(uint4*)&out[obase + (y0 + r) * IMG_W + x0] = pv;
}

// =============================================================================
extern "C" void kernel_launch(void* const* d_in, const int* in_sizes, int n_in,
                              void* d_out, int out_size) {
    const float* x     = (const float*)d_in[0];
    const float* n1w   = (const float*)d_in[1];
    const float* qkvw  = (const float*)d_in[2];
    const float* qkvdw = (const float*)d_in[3];
    const float* temp  = (const float*)d_in[4];
    const float* projw = (const float*)d_in[5];
    const float* n2w   = (const float*)d_in[6];
    const float* pinw  = (const float*)d_in[7];
    const float* dww   = (const float*)d_in[8];
    const float* poutw = (const float*)d_in[9];
    float* out = (float*)d_out;

    __nv_bfloat16 *S0b, *S1b, *S2b, *Wqkv, *Wproj, *Wpin, *Wpout;
    cudaGetSymbolAddress((void**)&S0b, g_S0b);
    cudaGetSymbolAddress((void**)&S1b, g_S1b);
    cudaGetSymbolAddress((void**)&S2b, g_S2b);
    cudaGetSymbolAddress((void**)&Wqkv, g_Wqkv);
    cudaGetSymbolAddress((void**)&Wproj, g_Wproj);
    cudaGetSymbolAddress((void**)&Wpin, g_Wpin);
    cudaGetSymbolAddress((void**)&Wpout, g_Wpout);

    dim3 pxGrid(HW / 256, BATCH);

    // ---- MDTA branch (order keeps qkv GEMM in ncu's capture slot) ----
    wconv_kernel<<<(576 * 192 + 255) / 256, 256>>>(qkvw, Wqkv, 576, 192, 576, 192);
    wconv_kernel<<<(192 * 192 + 255) / 256, 256>>>(projw, Wproj, 192, 192, 192, 192);
    ln_apply_kernel<<<pxGrid, 256>>>(x, n1w, S2b);

    // qkv 1x1: 576x192 -> bf16   (4th launch: ncu capture target)
    gemm_pipe<<<dim3(HW / 256, 9, BATCH), 256>>>(
        Wqkv, S2b, S0b, nullptr, 576, 192, (long long)DIM * HW, (long long)576 * HW, 1, 0);

    dw_qkv_kernel<<<dim3(NPART, 576, BATCH), 256>>>(S0b, qkvdw, S1b);
    attn_part_kernel<<<dim3(16, 16), 256>>>();
    attn_finish_kernel<<<16, 256>>>(temp);
    av_kernel<<<dim3(HW / 512, 16), 256>>>();

    // proj 1x1 (192x192): bf16 -> fp32 + residual(x)
    gemm_pipe<<<dim3(HW / 256, 3, BATCH), 256>>>(
        Wproj, S2b, out, x, 192, 192, (long long)DIM * HW, (long long)DIM * HW, 0, 1);

    // ---- GDFN branch ----
    wconv_kernel<<<(1024 * 192 + 255) / 256, 256>>>(pinw, Wpin, 1020, 192, 1024, 192);
    wconv_kernel<<<(192 * 512 + 255) / 256, 256>>>(poutw, Wpout, 192, 510, 192, 512);
    ln_apply_kernel<<<pxGrid, 256>>>(out, n2w, S2b);

    // pin 1x1 (1020x192 padded 1024): bf16 -> bf16
    gemm_pipe<<<dim3(HW / 256, 16, BATCH), 256>>>(
        Wpin, S2b, S0b, nullptr, 1020, 192, (long long)DIM * HW, (long long)1020 * HW, 1, 0);

    dw_gate_kernel<<<dim3(NPART, 512, BATCH), 256>>>(S0b, dww, S1b);

    // pout 1x1 (192x512 padded K): bf16 -> fp32 + residual(d_out)
    gemm_pipe<<<dim3(HW / 256, 3, BATCH), 256>>>(
        Wpout, S1b, out, out, 192, 512, (long long)512 * HW, (long long)DIM * HW, 0, 1);
}

// round 13
// speedup vs baseline: 1.5149x; 1.1057x over previous
#include <cuda_runtime.h>
#include <cuda_bf16.h>
#include <math.h>
#include <stdint.h>

#define HW 16384
#define IMG_W 128
#define DIM 192
#define HEADS 4
#define DHEAD 48
#define HIDDEN 510
#define BATCH 4
#define NPART 8

// ---------------- scratch (static device arrays) --------------------------------
__device__ __nv_bfloat16 g_S0b[BATCH * 1020 * HW]; // conv1x1 outputs (qkv:576 / pin:1020)
__device__ __nv_bfloat16 g_S1b[BATCH * 576 * HW];  // dw qkv out (576) / gated gdfn (512 pad)
__device__ __nv_bfloat16 g_S2b[BATCH * DIM * HW];  // LN-normalized xhat / attn output
__device__ __nv_bfloat16 g_Wqkv[576 * 192];
__device__ __nv_bfloat16 g_Wproj[192 * 192];
__device__ __nv_bfloat16 g_Wpin[1024 * 192];       // padded 1020->1024
__device__ __nv_bfloat16 g_Wpout[192 * 512];       // padded K 510->512
__device__ float g_rnpart[NPART * BATCH * 2 * DIM]; // [p][r]
__device__ float g_A[16 * DHEAD * DHEAD];
__device__ float g_Apart[16 * 16 * DHEAD * DHEAD];

// ---------------- helpers -------------------------------------------------------
__device__ __forceinline__ uint32_t pack_bf16(float x, float y) {
    __nv_bfloat162 h = __float22bfloat162_rn(make_float2(x, y));
    return *(uint32_t*)&h;
}
__device__ __forceinline__ uint32_t sm_addr(const void* p) {
    return (uint32_t)__cvta_generic_to_shared(p);
}
__device__ __forceinline__ void ldsm_x4(uint32_t* r, uint32_t addr) {
    asm volatile("ldmatrix.sync.aligned.m8n8.x4.shared.b16 {%0,%1,%2,%3}, [%4];"
        : "=r"(r[0]), "=r"(r[1]), "=r"(r[2]), "=r"(r[3]) : "r"(addr));
}
__device__ __forceinline__ void ldsm_x4t(uint32_t* r, uint32_t addr) {
    asm volatile("ldmatrix.sync.aligned.m8n8.x4.trans.shared.b16 {%0,%1,%2,%3}, [%4];"
        : "=r"(r[0]), "=r"(r[1]), "=r"(r[2]), "=r"(r[3]) : "r"(addr));
}
__device__ __forceinline__ void ldsm_x2(uint32_t* r, uint32_t addr) {
    asm volatile("ldmatrix.sync.aligned.m8n8.x2.shared.b16 {%0,%1}, [%2];"
        : "=r"(r[0]), "=r"(r[1]) : "r"(addr));
}
__device__ __forceinline__ void mma_bf16(float* d, const uint32_t* a, const uint32_t* b) {
    asm volatile("mma.sync.aligned.m16n8k16.row.col.f32.bf16.bf16.f32 "
        "{%0,%1,%2,%3}, {%4,%5,%6,%7}, {%8,%9}, {%0,%1,%2,%3};"
        : "+f"(d[0]), "+f"(d[1]), "+f"(d[2]), "+f"(d[3])
        : "r"(a[0]), "r"(a[1]), "r"(a[2]), "r"(a[3]), "r"(b[0]), "r"(b[1]));
}
__device__ __forceinline__ void cpa16(uint32_t dst, const void* src) {
    asm volatile("cp.async.cg.shared.global [%0], [%1], 16;" :: "r"(dst), "l"(src));
}
__device__ __forceinline__ void cpa_commit() { asm volatile("cp.async.commit_group;"); }
template<int N> __device__ __forceinline__ void cpa_wait() {
    asm volatile("cp.async.wait_group %0;" :: "n"(N));
}

// ---------------- weight fp32 -> bf16 with padding ------------------------------
__global__ __launch_bounds__(256) void wconv_kernel(const float* __restrict__ src,
                                                    __nv_bfloat16* __restrict__ dst,
                                                    int M, int K, int Mp, int Kp) {
    int idx = blockIdx.x * 256 + threadIdx.x;
    int tot = Mp * Kp;
    if (idx >= tot) return;
    int m = idx / Kp, k = idx - m * Kp;
    float v = (m < M && k < K) ? src[m * K + k] : 0.f;
    dst[idx] = __float2bfloat16(v);
}

// ---------------- LN: per-pixel stats + write normalized bf16 xhat ---------------
__global__ __launch_bounds__(256) void ln_apply_kernel(const float* __restrict__ x,
                                                       const float* __restrict__ lnW,
                                                       __nv_bfloat16* __restrict__ xh) {
    __shared__ float sw[DIM];
    int tid = threadIdx.x;
    if (tid < DIM) sw[tid] = lnW[tid];
    __syncthreads();
    int n = blockIdx.x * 256 + tid;
    int b = blockIdx.y;
    const float* xb = x + (long long)b * DIM * HW + n;
    float s = 0.f, s2 = 0.f;
#pragma unroll 8
    for (int c = 0; c < DIM; c++) {
        float v = xb[(long long)c * HW];
        s += v; s2 += v * v;
    }
    float m = s * (1.f / DIM);
    float var = s2 * (1.f / DIM) - m * m;
    float inv = rsqrtf(var + 1e-6f);
    __nv_bfloat16* ob = xh + (long long)b * DIM * HW + n;
#pragma unroll 8
    for (int c = 0; c < DIM; c++)
        ob[(long long)c * HW] = __float2bfloat16((xb[(long long)c * HW] - m) * inv * sw[c]);
}

// ---------------- bf16 GEMM (2-stage cp.async, BM64/BN256/BK32) -----------------
__global__ __launch_bounds__(256) void gemm_pipe(const __nv_bfloat16* __restrict__ Wb,
                                                 const __nv_bfloat16* __restrict__ X,
                                                 void* __restrict__ Outv,
                                                 const float* __restrict__ Res,
                                                 int M, int K,
                                                 long long xbs, long long obs,
                                                 int outBf16, int addRes) {
    __shared__ __align__(16) __nv_bfloat16 As[2][64][40];
    __shared__ __align__(16) __nv_bfloat16 Bs[2][32][264];
    int tid = threadIdx.x;
    int lane = tid & 31, wn = tid >> 5;
    int ra = lane >> 2, ca = lane & 3;
    int n0 = blockIdx.x * 256;
    int m0 = blockIdx.y * 64;
    int b  = blockIdx.z;
    const __nv_bfloat16* Xb = X + (long long)b * xbs;

    int ar = tid >> 2, ac = (tid & 3) * 8;

    float acc[4][4][4];
#pragma unroll
    for (int i = 0; i < 4; i++)
#pragma unroll
        for (int j = 0; j < 4; j++)
#pragma unroll
            for (int q = 0; q < 4; q++) acc[i][j][q] = 0.f;

    int nk = K >> 5;

    cpa16(sm_addr(&As[0][ar][ac]), &Wb[(long long)(m0 + ar) * K + ac]);
#pragma unroll
    for (int i = 0; i < 4; i++) {
        int chunk = tid + i * 256;
        int brow = chunk >> 5, bcol = (chunk & 31) * 8;
        cpa16(sm_addr(&Bs[0][brow][bcol]), &Xb[(long long)brow * HW + n0 + bcol]);
    }
    cpa_commit();

    for (int kt = 0; kt < nk; kt++) {
        if (kt + 1 < nk) {
            int s = (kt + 1) & 1;
            int k0 = (kt + 1) << 5;
            cpa16(sm_addr(&As[s][ar][ac]), &Wb[(long long)(m0 + ar) * K + k0 + ac]);
#pragma unroll
            for (int i = 0; i < 4; i++) {
                int chunk = tid + i * 256;
                int brow = chunk >> 5, bcol = (chunk & 31) * 8;
                cpa16(sm_addr(&Bs[s][brow][bcol]), &Xb[(long long)(k0 + brow) * HW + n0 + bcol]);
            }
        }
        cpa_commit();
        cpa_wait<1>();
        __syncthreads();
        int s = kt & 1;
#pragma unroll
        for (int ks = 0; ks < 2; ks++) {
            uint32_t afr[4][4], bfr[4][2];
#pragma unroll
            for (int tm = 0; tm < 4; tm++)
                ldsm_x4(afr[tm],
                    sm_addr(&As[s][tm * 16 + (lane & 15)][ks * 16 + (lane >> 4) * 8]));
#pragma unroll
            for (int tnp = 0; tnp < 2; tnp++) {
                uint32_t t4[4];
                ldsm_x4t(t4, sm_addr(&Bs[s][ks * 16 + (lane & 15)]
                                         [wn * 32 + tnp * 16 + (lane >> 4) * 8]));
                bfr[2 * tnp][0] = t4[0]; bfr[2 * tnp][1] = t4[1];
                bfr[2 * tnp + 1][0] = t4[2]; bfr[2 * tnp + 1][1] = t4[3];
            }
#pragma unroll
            for (int tm = 0; tm < 4; tm++)
#pragma unroll
                for (int tn = 0; tn < 4; tn++)
                    mma_bf16(acc[tm][tn], afr[tm], bfr[tn]);
        }
        __syncthreads();
    }

    if (outBf16) {
        __nv_bfloat16* Ob = (__nv_bfloat16*)Outv + (long long)b * obs;
#pragma unroll
        for (int tm = 0; tm < 4; tm++)
#pragma unroll
            for (int tn = 0; tn < 4; tn++) {
                int col = n0 + wn * 32 + tn * 8 + 2 * ca;
                int r0 = m0 + tm * 16 + ra;
                int r1 = r0 + 8;
                if (r0 < M)
                    *(uint32_t*)&Ob[(long long)r0 * HW + col] =
                        pack_bf16(acc[tm][tn][0], acc[tm][tn][1]);
                if (r1 < M)
                    *(uint32_t*)&Ob[(long long)r1 * HW + col] =
                        pack_bf16(acc[tm][tn][2], acc[tm][tn][3]);
            }
    } else {
        float* Ob = (float*)Outv + (long long)b * obs;
        const float* Rb = Res + (long long)b * obs;
#pragma unroll
        for (int tm = 0; tm < 4; tm++)
#pragma unroll
            for (int tn = 0; tn < 4; tn++) {
                int col = n0 + wn * 32 + tn * 8 + 2 * ca;
                int r0 = m0 + tm * 16 + ra;
                int r1 = r0 + 8;
                if (r0 < M) {
                    float2 v = make_float2(acc[tm][tn][0], acc[tm][tn][1]);
                    long long off = (long long)r0 * HW + col;
                    if (addRes) { float2 rr = *(const float2*)&Rb[off]; v.x += rr.x; v.y += rr.y; }
                    *(float2*)&Ob[off] = v;
                }
                if (r1 < M) {
                    float2 v = make_float2(acc[tm][tn][2], acc[tm][tn][3]);
                    long long off = (long long)r1 * HW + col;
                    if (addRes) { float2 rr = *(const float2*)&Rb[off]; v.x += rr.x; v.y += rr.y; }
                    *(float2*)&Ob[off] = v;
                }
            }
    }
}

// ---------------- depthwise 3x3 qkv: vectorized 16-row tiles --------------------
__global__ __launch_bounds__(256) void dw_qkv_kernel(const __nv_bfloat16* __restrict__ in,
                                                     const float* __restrict__ w9,
                                                     __nv_bfloat16* __restrict__ out) {
    __shared__ __nv_bfloat16 st[18][136];
    __shared__ float red[256];
    int c = blockIdx.y, b = blockIdx.z;
    long long base = ((long long)b * 576 + c) * HW;
    int y0 = blockIdx.x * 16;
    int tid = threadIdx.x;
    float w[9];
#pragma unroll
    for (int i = 0; i < 9; i++) w[i] = w9[c * 9 + i];

    for (int id = tid; id < 288; id += 256) {
        int r = id >> 4, c8 = (id & 15) * 8;
        int gy = y0 - 1 + r;
        uint4 v = make_uint4(0u, 0u, 0u, 0u);
        if ((unsigned)gy < IMG_W) v = *(const uint4*)&in[base + gy * IMG_W + c8];
        *(uint4*)&st[r][c8] = v;
    }
    __syncthreads();

    int r = tid >> 4, x0 = (tid & 15) * 8;
    float o[8] = {};
#pragma unroll
    for (int ky = 0; ky < 3; ky++) {
        float t[10];
#pragma unroll
        for (int i = 0; i < 10; i++) {
            int xx = x0 - 1 + i;
            t[i] = ((unsigned)xx < IMG_W) ? __bfloat162float(st[r + ky][xx]) : 0.f;
        }
        float w0 = w[ky * 3], w1 = w[ky * 3 + 1], w2 = w[ky * 3 + 2];
#pragma unroll
        for (int j = 0; j < 8; j++)
            o[j] += w0 * t[j] + w1 * t[j + 1] + w2 * t[j + 2];
    }
    uint4 pv;
    uint32_t* pp = (uint32_t*)&pv;
#pragma unroll
    for (int i = 0; i < 4; i++) pp[i] = pack_bf16(o[2 * i], o[2 * i + 1]);
    *(uint4*)&out[base + (y0 + r) * IMG_W + x0] = pv;

    if (c < 384) {
        float ss = 0.f;
#pragma unroll
        for (int j = 0; j < 8; j++) ss += o[j] * o[j];
        red[tid] = ss;
        __syncthreads();
        for (int stp = 128; stp; stp >>= 1) {
            if (tid < stp) red[tid] += red[tid + stp];
            __syncthreads();
        }
        if (tid == 0)
            g_rnpart[(long long)blockIdx.x * (BATCH * 384) + b * 384 + c] = red[0];
    }
}

// ---------------- split-K partial Q.K^T via tensor cores ------------------------
// grid (16 chunks, 16 bh), 256 threads; warps 0-5 active for MMA (3 mtile x 2 nhalf)
__global__ __launch_bounds__(256) void attn_part_kernel() {
    __shared__ __align__(16) __nv_bfloat16 Qs[48][72];
    __shared__ __align__(16) __nv_bfloat16 Ks[48][72];
    int chunk = blockIdx.x;
    int bh = blockIdx.y;
    int b = bh >> 2, h = bh & 3;
    const __nv_bfloat16* qb = g_S1b + ((long long)b * 576 + h * DHEAD) * HW;
    const __nv_bfloat16* kb = g_S1b + ((long long)b * 576 + DIM + h * DHEAD) * HW;
    int tid = threadIdx.x, lane = tid & 31, w = tid >> 5;
    int mt = w >> 1, nh = w & 1;         // valid for w<6
    int ra = lane >> 2, ca = lane & 3;
    long long nbase = (long long)chunk * 1024;

    float acc[3][4] = {};

    for (int sl = 0; sl < 16; sl++) {
        long long nb = nbase + sl * 64;
        // load Q,K 48x64 slabs: 768 chunks of 16B, 3 per thread
#pragma unroll
        for (int i = 0; i < 3; i++) {
            int id = tid + i * 256;      // 0..767
            int r = id >> 3;             // 0..95  (FIXED: no &63 wrap)
            int c8 = (id & 7) * 8;
            if (r < 48)
                cpa16(sm_addr(&Qs[r][c8]), &qb[(long long)r * HW + nb + c8]);
            else
                cpa16(sm_addr(&Ks[r - 48][c8]), &kb[(long long)(r - 48) * HW + nb + c8]);
        }
        cpa_commit();
        cpa_wait<0>();
        __syncthreads();
        if (w < 6) {
#pragma unroll
            for (int kp = 0; kp < 4; kp++) {
                uint32_t afr[4], bfr[3][2];
                ldsm_x4(afr, sm_addr(&Qs[mt * 16 + (lane & 15)][kp * 16 + (lane >> 4) * 8]));
#pragma unroll
                for (int tn = 0; tn < 3; tn++)
                    ldsm_x2(bfr[tn], sm_addr(&Ks[nh * 24 + tn * 8 + (lane & 7)]
                                                [kp * 16 + ((lane >> 3) & 1) * 8]));
#pragma unroll
                for (int tn = 0; tn < 3; tn++)
                    mma_bf16(acc[tn], afr, bfr[tn]);
            }
        }
        __syncthreads();
    }
    if (w < 6) {
        float* P = g_Apart + ((long long)bh * 16 + chunk) * (DHEAD * DHEAD);
#pragma unroll
        for (int tn = 0; tn < 3; tn++) {
            int d0 = nh * 24 + tn * 8 + 2 * ca;
            int c0 = mt * 16 + ra;
            *(float2*)&P[c0 * DHEAD + d0] = make_float2(acc[tn][0], acc[tn][1]);
            *(float2*)&P[(c0 + 8) * DHEAD + d0] = make_float2(acc[tn][2], acc[tn][3]);
        }
    }
}

// ---------------- reduce partials + rownorms, scale, softmax --------------------
__global__ __launch_bounds__(256) void attn_finish_kernel(const float* __restrict__ temp) {
    int bh = blockIdx.x;
    int b = bh >> 2, h = bh & 3;
    __shared__ float sA[DHEAD * DHEAD];
    __shared__ float srn_q[DHEAD], srn_k[DHEAD];
    int tid = threadIdx.x;
    if (tid < 96) {
        int i = tid;
        int isK = (i >= DHEAD);
        int cc = i - isK * DHEAD;
        int row = b * 384 + isK * DIM + h * DHEAD + cc;
        float s = 0.f;
#pragma unroll
        for (int p = 0; p < NPART; p++) s += g_rnpart[(long long)p * (BATCH * 384) + row];
        float v = 1.f / fmaxf(sqrtf(s), 1e-12f);
        if (isK) srn_k[cc] = v; else srn_q[cc] = v;
    }
    __syncthreads();
    for (int i = tid; i < DHEAD * DHEAD; i += 256) {
        float s = 0.f;
        for (int p = 0; p < 16; p++)
            s += g_Apart[((long long)bh * 16 + p) * (DHEAD * DHEAD) + i];
        int c = i / DHEAD, d = i % DHEAD;
        sA[i] = s * srn_q[c] * srn_k[d] * temp[h];
    }
    __syncthreads();
    if (tid < DHEAD) {
        float mx = -1e30f;
        for (int d = 0; d < DHEAD; d++) mx = fmaxf(mx, sA[tid * DHEAD + d]);
        float sum = 0.f;
        for (int d = 0; d < DHEAD; d++) sum += __expf(sA[tid * DHEAD + d] - mx);
        float inv = 1.f / sum;
        for (int d = 0; d < DHEAD; d++)
            g_A[bh * DHEAD * DHEAD + tid * DHEAD + d] =
                __expf(sA[tid * DHEAD + d] - mx) * inv;
    }
}

// ---------------- out = A @ V via tensor cores ----------------------------------
// grid (HW/256, 16 bh), 256 threads; warp owns 48 x 32-col slice.
__global__ __launch_bounds__(256) void av_kernel() {
    __shared__ __align__(16) __nv_bfloat16 Ab[48][56];
    __shared__ __align__(16) __nv_bfloat16 Vs[48][264];
    int bh = blockIdx.y;
    int b = bh >> 2, h = bh & 3;
    int tid = threadIdx.x, lane = tid & 31, wn = tid >> 5;
    int ra = lane >> 2, ca = lane & 3;
    int n0 = blockIdx.x * 256;

    for (int i = tid; i < DHEAD * DHEAD; i += 256)
        Ab[i / DHEAD][i % DHEAD] = __float2bfloat16(g_A[bh * DHEAD * DHEAD + i]);

    const __nv_bfloat16* vb = g_S1b + ((long long)b * 576 + 2 * DIM + h * DHEAD) * HW;
#pragma unroll
    for (int i = 0; i < 6; i++) {
        int id = tid + i * 256;   // 1536 chunks: 48 rows x 32
        int d = id >> 5, c8 = (id & 31) * 8;
        cpa16(sm_addr(&Vs[d][c8]), &vb[(long long)d * HW + n0 + c8]);
    }
    cpa_commit();
    cpa_wait<0>();
    __syncthreads();

    float acc[3][4][4];
#pragma unroll
    for (int i = 0; i < 3; i++)
#pragma unroll
        for (int j = 0; j < 4; j++)
#pragma unroll
            for (int q = 0; q < 4; q++) acc[i][j][q] = 0.f;

#pragma unroll
    for (int ks = 0; ks < 3; ks++) {
        uint32_t afr[3][4], bfr[4][2];
#pragma unroll
        for (int mt = 0; mt < 3; mt++)
            ldsm_x4(afr[mt], sm_addr(&Ab[mt * 16 + (lane & 15)][ks * 16 + (lane >> 4) * 8]));
#pragma unroll
        for (int tnp = 0; tnp < 2; tnp++) {
            uint32_t t4[4];
            ldsm_x4t(t4, sm_addr(&Vs[ks * 16 + (lane & 15)]
                                    [wn * 32 + tnp * 16 + (lane >> 4) * 8]));
            bfr[2 * tnp][0] = t4[0]; bfr[2 * tnp][1] = t4[1];
            bfr[2 * tnp + 1][0] = t4[2]; bfr[2 * tnp + 1][1] = t4[3];
        }
#pragma unroll
        for (int mt = 0; mt < 3; mt++)
#pragma unroll
            for (int tn = 0; tn < 4; tn++)
                mma_bf16(acc[mt][tn], afr[mt], bfr[tn]);
    }

    __nv_bfloat16* ob = g_S2b + ((long long)b * DIM + h * DHEAD) * HW;
#pragma unroll
    for (int mt = 0; mt < 3; mt++)
#pragma unroll
        for (int tn = 0; tn < 4; tn++) {
            int col = n0 + wn * 32 + tn * 8 + 2 * ca;
            int c0 = mt * 16 + ra;
            *(uint32_t*)&ob[(long long)c0 * HW + col] =
                pack_bf16(acc[mt][tn][0], acc[mt][tn][1]);
            *(uint32_t*)&ob[(long long)(c0 + 8) * HW + col] =
                pack_bf16(acc[mt][tn][2], acc[mt][tn][3]);
        }
}

// ---------------- fused GDFN dw3x3 + GELU gate: vectorized 16-row tiles ---------
__global__ __launch_bounds__(256) void dw_gate_kernel(const __nv_bfloat16* __restrict__ in,
                                                      const float* __restrict__ w9,
                                                      __nv_bfloat16* __restrict__ out) {
    __shared__ __nv_bfloat16 st1[18][136], st2[18][136];
    int c = blockIdx.y, b = blockIdx.z;
    int y0 = blockIdx.x * 16;
    int tid = threadIdx.x;
    int r = tid >> 4, x0 = (tid & 15) * 8;
    long long obase = ((long long)b * 512 + c) * HW;

    if (c >= HIDDEN) {
        uint4 z = make_uint4(0u, 0u, 0u, 0u);
        *(uint4*)&out[obase + (y0 + r) * IMG_W + x0] = z;
        return;
    }
    long long base1 = ((long long)b * 1020 + c) * HW;
    long long base2 = ((long long)b * 1020 + HIDDEN + c) * HW;
    float w1[9], w2[9];
#pragma unroll
    for (int i = 0; i < 9; i++) { w1[i] = w9[c * 9 + i]; w2[i] = w9[(HIDDEN + c) * 9 + i]; }

    for (int id = tid; id < 288; id += 256) {
        int rr = id >> 4, c8 = (id & 15) * 8;
        int gy = y0 - 1 + rr;
        uint4 v1 = make_uint4(0u, 0u, 0u, 0u), v2 = v1;
        if ((unsigned)gy < IMG_W) {
            v1 = *(const uint4*)&in[base1 + gy * IMG_W + c8];
            v2 = *(const uint4*)&in[base2 + gy * IMG_W + c8];
        }
        *(uint4*)&st1[rr][c8] = v1;
        *(uint4*)&st2[rr][c8] = v2;
    }
    __syncthreads();

    float o1[8] = {}, o2[8] = {};
#pragma unroll
    for (int ky = 0; ky < 3; ky++) {
        float t1[10], t2[10];
#pragma unroll
        for (int i = 0; i < 10; i++) {
            int xx = x0 - 1 + i;
            bool ok = (unsigned)xx < IMG_W;
            t1[i] = ok ? __bfloat162float(st1[r + ky][xx]) : 0.f;
            t2[i] = ok ? __bfloat162float(st2[r + ky][xx]) : 0.f;
        }
        float a0 = w1[ky * 3], a1 = w1[ky * 3 + 1], a2 = w1[ky * 3 + 2];
        float b0 = w2[ky * 3], b1 = w2[ky * 3 + 1], b2 = w2[ky * 3 + 2];
#pragma unroll
        for (int j = 0; j < 8; j++) {
            o1[j] += a0 * t1[j] + a1 * t1[j + 1] + a2 * t1[j + 2];
            o2[j] += b0 * t2[j] + b1 * t2[j + 1] + b2 * t2[j + 2];
        }
    }
    uint4 pv;
    uint32_t* pp = (uint32_t*)&pv;
#pragma unroll
    for (int i = 0; i < 4; i++) {
        float g0 = 0.5f * o1[2 * i] * (1.f + erff(o1[2 * i] * 0.70710678118654752f));
        float g1 = 0.5f * o1[2 * i + 1] * (1.f + erff(o1[2 * i + 1] * 0.70710678118654752f));
        pp[i] = pack_bf16(g0 * o2[2 * i], g1 * o2[2 * i + 1]);
    }
    *(uint4*)&out[obase + (y0 + r) * IMG_W + x0] = pv;
}

// =============================================================================
extern "C" void kernel_launch(void* const* d_in, const int* in_sizes, int n_in,
                              void* d_out, int out_size) {
    const float* x     = (const float*)d_in[0];
    const float* n1w   = (const float*)d_in[1];
    const float* qkvw  = (const float*)d_in[2];
    const float* qkvdw = (const float*)d_in[3];
    const float* temp  = (const float*)d_in[4];
    const float* projw = (const float*)d_in[5];
    const float* n2w   = (const float*)d_in[6];
    const float* pinw  = (const float*)d_in[7];
    const float* dww   = (const float*)d_in[8];
    const float* poutw = (const float*)d_in[9];
    float* out = (float*)d_out;

    __nv_bfloat16 *S0b, *S1b, *S2b, *Wqkv, *Wproj, *Wpin, *Wpout;
    cudaGetSymbolAddress((void**)&S0b, g_S0b);
    cudaGetSymbolAddress((void**)&S1b, g_S1b);
    cudaGetSymbolAddress((void**)&S2b, g_S2b);
    cudaGetSymbolAddress((void**)&Wqkv, g_Wqkv);
    cudaGetSymbolAddress((void**)&Wproj, g_Wproj);
    cudaGetSymbolAddress((void**)&Wpin, g_Wpin);
    cudaGetSymbolAddress((void**)&Wpout, g_Wpout);

    dim3 pxGrid(HW / 256, BATCH);

    // ---- MDTA branch (order keeps qkv GEMM in ncu's capture slot) ----
    wconv_kernel<<<(576 * 192 + 255) / 256, 256>>>(qkvw, Wqkv, 576, 192, 576, 192);
    wconv_kernel<<<(192 * 192 + 255) / 256, 256>>>(projw, Wproj, 192, 192, 192, 192);
    ln_apply_kernel<<<pxGrid, 256>>>(x, n1w, S2b);

    // qkv 1x1: 576x192 -> bf16   (4th launch: ncu capture target)
    gemm_pipe<<<dim3(HW / 256, 9, BATCH), 256>>>(
        Wqkv, S2b, S0b, nullptr, 576, 192, (long long)DIM * HW, (long long)576 * HW, 1, 0);

    dw_qkv_kernel<<<dim3(NPART, 576, BATCH), 256>>>(S0b, qkvdw, S1b);
    attn_part_kernel<<<dim3(16, 16), 256>>>();
    attn_finish_kernel<<<16, 256>>>(temp);
    av_kernel<<<dim3(HW / 256, 16), 256>>>();

    // proj 1x1 (192x192): bf16 -> fp32 + residual(x)
    gemm_pipe<<<dim3(HW / 256, 3, BATCH), 256>>>(
        Wproj, S2b, out, x, 192, 192, (long long)DIM * HW, (long long)DIM * HW, 0, 1);

    // ---- GDFN branch ----
    wconv_kernel<<<(1024 * 192 + 255) / 256, 256>>>(pinw, Wpin, 1020, 192, 1024, 192);
    wconv_kernel<<<(192 * 512 + 255) / 256, 256>>>(poutw, Wpout, 192, 510, 192, 512);
    ln_apply_kernel<<<pxGrid, 256>>>(out, n2w, S2b);

    // pin 1x1 (1020x192 padded 1024): bf16 -> bf16
    gemm_pipe<<<dim3(HW / 256, 16, BATCH), 256>>>(
        Wpin, S2b, S0b, nullptr, 1020, 192, (long long)DIM * HW, (long long)1020 * HW, 1, 0);

    dw_gate_kernel<<<dim3(NPART, 512, BATCH), 256>>>(S0b, dww, S1b);

    // pout 1x1 (192x512 padded K): bf16 -> fp32 + residual(d_out)
    gemm_pipe<<<dim3(HW / 256, 3, BATCH), 256>>>(
        Wpout, S1b, out, out, 192, 512, (long long)512 * HW, (long long)DIM * HW, 0, 1);
}

// round 14
// speedup vs baseline: 1.6458x; 1.0864x over previous
#include <cuda_runtime.h>
#include <cuda_fp16.h>
#include <math.h>
#include <stdint.h>

#define HW 16384
#define IMG_W 128
#define DIM 192
#define HEADS 4
#define DHEAD 48
#define HIDDEN 510
#define BATCH 4
#define NPART 8

// ---------------- scratch (static device arrays) --------------------------------
__device__ __half g_S0h[BATCH * 1020 * HW]; // conv1x1 outputs (qkv:576 / pin:1020)
__device__ __half g_S1h[BATCH * 576 * HW];  // dw qkv out (576) / gated gdfn (512 pad)
__device__ __half g_S2h[BATCH * DIM * HW];  // LN-normalized xhat / attn output
__device__ __half g_Wqkv[640 * 192];        // padded 576->640
__device__ __half g_Wproj[256 * 192];       // padded 192->256
__device__ __half g_Wpin[1024 * 192];       // padded 1020->1024
__device__ __half g_Wpout[256 * 512];       // padded 192->256, K 510->512
__device__ float g_rnpart[NPART * BATCH * 2 * DIM]; // [p][r]
__device__ float g_A[16 * DHEAD * DHEAD];
__device__ float g_Apart[16 * 16 * DHEAD * DHEAD];

// ---------------- helpers -------------------------------------------------------
__device__ __forceinline__ uint32_t pack_h2(float x, float y) {
    __half2 h = __floats2half2_rn(x, y);
    return *(uint32_t*)&h;
}
__device__ __forceinline__ uint32_t sm_addr(const void* p) {
    return (uint32_t)__cvta_generic_to_shared(p);
}
__device__ __forceinline__ void ldsm_x4(uint32_t* r, uint32_t addr) {
    asm volatile("ldmatrix.sync.aligned.m8n8.x4.shared.b16 {%0,%1,%2,%3}, [%4];"
        : "=r"(r[0]), "=r"(r[1]), "=r"(r[2]), "=r"(r[3]) : "r"(addr));
}
__device__ __forceinline__ void ldsm_x4t(uint32_t* r, uint32_t addr) {
    asm volatile("ldmatrix.sync.aligned.m8n8.x4.trans.shared.b16 {%0,%1,%2,%3}, [%4];"
        : "=r"(r[0]), "=r"(r[1]), "=r"(r[2]), "=r"(r[3]) : "r"(addr));
}
__device__ __forceinline__ void ldsm_x2(uint32_t* r, uint32_t addr) {
    asm volatile("ldmatrix.sync.aligned.m8n8.x2.shared.b16 {%0,%1}, [%2];"
        : "=r"(r[0]), "=r"(r[1]) : "r"(addr));
}
// fp16 accumulate MMA (2x rate, half registers)
__device__ __forceinline__ void mma_f16acc(uint32_t* d, const uint32_t* a, const uint32_t* b) {
    asm volatile("mma.sync.aligned.m16n8k16.row.col.f16.f16.f16.f16 "
        "{%0,%1}, {%2,%3,%4,%5}, {%6,%7}, {%0,%1};"
        : "+r"(d[0]), "+r"(d[1])
        : "r"(a[0]), "r"(a[1]), "r"(a[2]), "r"(a[3]), "r"(b[0]), "r"(b[1]));
}
// fp32 accumulate MMA with fp16 inputs (attention)
__device__ __forceinline__ void mma_f32acc(float* d, const uint32_t* a, const uint32_t* b) {
    asm volatile("mma.sync.aligned.m16n8k16.row.col.f32.f16.f16.f32 "
        "{%0,%1,%2,%3}, {%4,%5,%6,%7}, {%8,%9}, {%0,%1,%2,%3};"
        : "+f"(d[0]), "+f"(d[1]), "+f"(d[2]), "+f"(d[3])
        : "r"(a[0]), "r"(a[1]), "r"(a[2]), "r"(a[3]), "r"(b[0]), "r"(b[1]));
}
__device__ __forceinline__ void cpa16(uint32_t dst, const void* src) {
    asm volatile("cp.async.cg.shared.global [%0], [%1], 16;" :: "r"(dst), "l"(src));
}
__device__ __forceinline__ void cpa_commit() { asm volatile("cp.async.commit_group;"); }
template<int N> __device__ __forceinline__ void cpa_wait() {
    asm volatile("cp.async.wait_group %0;" :: "n"(N));
}

// ---------------- weight fp32 -> fp16 with padding ------------------------------
__global__ __launch_bounds__(256) void wconv_kernel(const float* __restrict__ src,
                                                    __half* __restrict__ dst,
                                                    int M, int K, int Mp, int Kp) {
    int idx = blockIdx.x * 256 + threadIdx.x;
    int tot = Mp * Kp;
    if (idx >= tot) return;
    int m = idx / Kp, k = idx - m * Kp;
    float v = (m < M && k < K) ? src[m * K + k] : 0.f;
    dst[idx] = __float2half(v);
}

// ---------------- LN: per-pixel stats + write normalized fp16 xhat ---------------
__global__ __launch_bounds__(256) void ln_apply_kernel(const float* __restrict__ x,
                                                       const float* __restrict__ lnW,
                                                       __half* __restrict__ xh) {
    __shared__ float sw[DIM];
    int tid = threadIdx.x;
    if (tid < DIM) sw[tid] = lnW[tid];
    __syncthreads();
    int n = blockIdx.x * 256 + tid;
    int b = blockIdx.y;
    const float* xb = x + (long long)b * DIM * HW + n;
    float s = 0.f, s2 = 0.f;
#pragma unroll 8
    for (int c = 0; c < DIM; c++) {
        float v = xb[(long long)c * HW];
        s += v; s2 += v * v;
    }
    float m = s * (1.f / DIM);
    float var = s2 * (1.f / DIM) - m * m;
    float inv = rsqrtf(var + 1e-6f);
    __half* ob = xh + (long long)b * DIM * HW + n;
#pragma unroll 8
    for (int c = 0; c < DIM; c++)
        ob[(long long)c * HW] = __float2half((xb[(long long)c * HW] - m) * inv * sw[c]);
}

// ---------------- fp16 GEMM: BM=128, BN=256, BK=32, fp16 accum ------------------
// Out[b,m,n] = sum_k Wb[m,k]*X[k,n] (+Res). K mult of 32; Wb padded to 128-mult M.
#define ASTR 40
#define BSTR 264
#define ABYTES (128 * ASTR * 2)
#define BBYTES (32 * BSTR * 2)
#define GSMEM (2 * (ABYTES + BBYTES))

__global__ __launch_bounds__(256) void gemm_fp16(const __half* __restrict__ Wb,
                                                 const __half* __restrict__ X,
                                                 void* __restrict__ Outv,
                                                 const float* __restrict__ Res,
                                                 int M, int K,
                                                 long long xbs, long long obs,
                                                 int outF16, int addRes) {
    extern __shared__ __align__(16) uint8_t dynsm[];
    uint32_t aBase = sm_addr(dynsm);
    uint32_t bBase = aBase + 2 * ABYTES;
    const __half* AsG = (const __half*)dynsm;            // generic-ptr views
    int tid = threadIdx.x, lane = tid & 31, wid = tid >> 5;
    int wm = wid & 1, wn = wid >> 1;       // 2(M) x 4(N)
    int ra = lane >> 2, ca = lane & 3;
    int n0 = blockIdx.x * 256;
    int m0 = blockIdx.y * 128;
    int b  = blockIdx.z;
    const __half* Xb = X + (long long)b * xbs;
    (void)AsG;

    uint32_t acc[4][8][2];
#pragma unroll
    for (int i = 0; i < 4; i++)
#pragma unroll
        for (int j = 0; j < 8; j++) { acc[i][j][0] = 0u; acc[i][j][1] = 0u; }

    int nk = K >> 5;

    auto load_slab = [&](int kt, int s) {
        int kb = kt << 5;
        uint32_t aS = aBase + s * ABYTES;
        uint32_t bS = bBase + s * BBYTES;
#pragma unroll
        for (int i = 0; i < 2; i++) {
            int id = tid + i * 256;              // 512 chunks: 128m x 4
            int m = id >> 2, kc = (id & 3) * 8;
            cpa16(aS + (uint32_t)(m * ASTR + kc) * 2,
                  &Wb[(long long)(m0 + m) * K + kb + kc]);
        }
#pragma unroll
        for (int i = 0; i < 4; i++) {
            int id = tid + i * 256;              // 1024 chunks: 32k x 32
            int kr = id >> 5, nc = (id & 31) * 8;
            cpa16(bS + (uint32_t)(kr * BSTR + nc) * 2,
                  &Xb[(long long)(kb + kr) * HW + n0 + nc]);
        }
    };

    load_slab(0, 0);
    cpa_commit();

    for (int kt = 0; kt < nk; kt++) {
        if (kt + 1 < nk) load_slab(kt + 1, (kt + 1) & 1);
        cpa_commit();
        cpa_wait<1>();
        __syncthreads();
        int s = kt & 1;
        uint32_t aS = aBase + s * ABYTES;
        uint32_t bS = bBase + s * BBYTES;
#pragma unroll
        for (int ks = 0; ks < 2; ks++) {
            uint32_t afr[4][4], bfr[8][2];
#pragma unroll
            for (int tm = 0; tm < 4; tm++)
                ldsm_x4(afr[tm], aS + (uint32_t)((wm * 64 + tm * 16 + (lane & 15)) * ASTR
                                                 + ks * 16 + (lane >> 4) * 8) * 2);
#pragma unroll
            for (int tnp = 0; tnp < 4; tnp++) {
                uint32_t t4[4];
                ldsm_x4t(t4, bS + (uint32_t)((ks * 16 + (lane & 15)) * BSTR
                                             + wn * 64 + tnp * 16 + (lane >> 4) * 8) * 2);
                bfr[2 * tnp][0] = t4[0]; bfr[2 * tnp][1] = t4[1];
                bfr[2 * tnp + 1][0] = t4[2]; bfr[2 * tnp + 1][1] = t4[3];
            }
#pragma unroll
            for (int tm = 0; tm < 4; tm++)
#pragma unroll
                for (int tn = 0; tn < 8; tn++)
                    mma_f16acc(acc[tm][tn], afr[tm], bfr[tn]);
        }
        __syncthreads();
    }

    if (outF16) {
        __half* Ob = (__half*)Outv + (long long)b * obs;
#pragma unroll
        for (int tm = 0; tm < 4; tm++)
#pragma unroll
            for (int tn = 0; tn < 8; tn++) {
                int col = n0 + wn * 64 + tn * 8 + 2 * ca;
                int r0 = m0 + wm * 64 + tm * 16 + ra;
                int r1 = r0 + 8;
                if (r0 < M) *(uint32_t*)&Ob[(long long)r0 * HW + col] = acc[tm][tn][0];
                if (r1 < M) *(uint32_t*)&Ob[(long long)r1 * HW + col] = acc[tm][tn][1];
            }
    } else {
        float* Ob = (float*)Outv + (long long)b * obs;
        const float* Rb = Res + (long long)b * obs;
#pragma unroll
        for (int tm = 0; tm < 4; tm++)
#pragma unroll
            for (int tn = 0; tn < 8; tn++) {
                int col = n0 + wn * 64 + tn * 8 + 2 * ca;
                int r0 = m0 + wm * 64 + tm * 16 + ra;
                int r1 = r0 + 8;
                if (r0 < M) {
                    float2 v = __half22float2(*(__half2*)&acc[tm][tn][0]);
                    long long off = (long long)r0 * HW + col;
                    if (addRes) { float2 rr = *(const float2*)&Rb[off]; v.x += rr.x; v.y += rr.y; }
                    *(float2*)&Ob[off] = v;
                }
                if (r1 < M) {
                    float2 v = __half22float2(*(__half2*)&acc[tm][tn][1]);
                    long long off = (long long)r1 * HW + col;
                    if (addRes) { float2 rr = *(const float2*)&Rb[off]; v.x += rr.x; v.y += rr.y; }
                    *(float2*)&Ob[off] = v;
                }
            }
    }
}

// ---------------- depthwise 3x3 qkv: vectorized 16-row tiles --------------------
__global__ __launch_bounds__(256) void dw_qkv_kernel(const __half* __restrict__ in,
                                                     const float* __restrict__ w9,
                                                     __half* __restrict__ out) {
    __shared__ __half st[18][136];
    __shared__ float red[256];
    int c = blockIdx.y, b = blockIdx.z;
    long long base = ((long long)b * 576 + c) * HW;
    const __half* ib = in + base;
    int y0 = blockIdx.x * 16;
    int tid = threadIdx.x;
    float w[9];
#pragma unroll
    for (int i = 0; i < 9; i++) w[i] = w9[c * 9 + i];

    for (int id = tid; id < 288; id += 256) {
        int r = id >> 4, c8 = (id & 15) * 8;
        int gy = y0 - 1 + r;
        uint4 v = make_uint4(0u, 0u, 0u, 0u);
        if ((unsigned)gy < IMG_W) v = *(const uint4*)&ib[gy * IMG_W + c8];
        *(uint4*)&st[r][c8] = v;
    }
    __syncthreads();

    int r = tid >> 4, x0 = (tid & 15) * 8;
    float o[8] = {};
#pragma unroll
    for (int ky = 0; ky < 3; ky++) {
        float t[10];
#pragma unroll
        for (int i = 0; i < 10; i++) {
            int xx = x0 - 1 + i;
            t[i] = ((unsigned)xx < IMG_W) ? __half2float(st[r + ky][xx]) : 0.f;
        }
        float w0 = w[ky * 3], w1 = w[ky * 3 + 1], w2 = w[ky * 3 + 2];
#pragma unroll
        for (int j = 0; j < 8; j++)
            o[j] += w0 * t[j] + w1 * t[j + 1] + w2 * t[j + 2];
    }
    uint4 pv;
    uint32_t* pp = (uint32_t*)&pv;
#pragma unroll
    for (int i = 0; i < 4; i++) pp[i] = pack_h2(o[2 * i], o[2 * i + 1]);
    *(uint4*)&out[base + (y0 + r) * IMG_W + x0] = pv;

    if (c < 384) {
        float ss = 0.f;
#pragma unroll
        for (int j = 0; j < 8; j++) ss += o[j] * o[j];
        red[tid] = ss;
        __syncthreads();
        for (int stp = 128; stp; stp >>= 1) {
            if (tid < stp) red[tid] += red[tid + stp];
            __syncthreads();
        }
        if (tid == 0)
            g_rnpart[(long long)blockIdx.x * (BATCH * 384) + b * 384 + c] = red[0];
    }
}

// ---------------- split-K partial Q.K^T via tensor cores ------------------------
__global__ __launch_bounds__(256) void attn_part_kernel() {
    __shared__ __align__(16) __half Qs[48][72];
    __shared__ __align__(16) __half Ks[48][72];
    int chunk = blockIdx.x;
    int bh = blockIdx.y;
    int b = bh >> 2, h = bh & 3;
    const __half* qb = g_S1h + ((long long)b * 576 + h * DHEAD) * HW;
    const __half* kb = g_S1h + ((long long)b * 576 + DIM + h * DHEAD) * HW;
    int tid = threadIdx.x, lane = tid & 31, w = tid >> 5;
    int mt = w >> 1, nh = w & 1;
    int ra = lane >> 2, ca = lane & 3;
    long long nbase = (long long)chunk * 1024;

    float acc[3][4] = {};

    for (int sl = 0; sl < 16; sl++) {
        long long nb = nbase + sl * 64;
#pragma unroll
        for (int i = 0; i < 3; i++) {
            int id = tid + i * 256;      // 0..767
            int r = id >> 3;             // 0..95
            int c8 = (id & 7) * 8;
            if (r < 48)
                cpa16(sm_addr(&Qs[r][c8]), &qb[(long long)r * HW + nb + c8]);
            else
                cpa16(sm_addr(&Ks[r - 48][c8]), &kb[(long long)(r - 48) * HW + nb + c8]);
        }
        cpa_commit();
        cpa_wait<0>();
        __syncthreads();
        if (w < 6) {
#pragma unroll
            for (int kp = 0; kp < 4; kp++) {
                uint32_t afr[4], bfr[3][2];
                ldsm_x4(afr, sm_addr(&Qs[mt * 16 + (lane & 15)][kp * 16 + (lane >> 4) * 8]));
#pragma unroll
                for (int tn = 0; tn < 3; tn++)
                    ldsm_x2(bfr[tn], sm_addr(&Ks[nh * 24 + tn * 8 + (lane & 7)]
                                                [kp * 16 + ((lane >> 3) & 1) * 8]));
#pragma unroll
                for (int tn = 0; tn < 3; tn++)
                    mma_f32acc(acc[tn], afr, bfr[tn]);
            }
        }
        __syncthreads();
    }
    if (w < 6) {
        float* P = g_Apart + ((long long)bh * 16 + chunk) * (DHEAD * DHEAD);
#pragma unroll
        for (int tn = 0; tn < 3; tn++) {
            int d0 = nh * 24 + tn * 8 + 2 * ca;
            int c0 = mt * 16 + ra;
            *(float2*)&P[c0 * DHEAD + d0] = make_float2(acc[tn][0], acc[tn][1]);
            *(float2*)&P[(c0 + 8) * DHEAD + d0] = make_float2(acc[tn][2], acc[tn][3]);
        }
    }
}

// ---------------- reduce partials + rownorms, scale, softmax --------------------
__global__ __launch_bounds__(256) void attn_finish_kernel(const float* __restrict__ temp) {
    int bh = blockIdx.x;
    int b = bh >> 2, h = bh & 3;
    __shared__ float sA[DHEAD * DHEAD];
    __shared__ float srn_q[DHEAD], srn_k[DHEAD];
    int tid = threadIdx.x;
    if (tid < 96) {
        int i = tid;
        int isK = (i >= DHEAD);
        int cc = i - isK * DHEAD;
        int row = b * 384 + isK * DIM + h * DHEAD + cc;
        float s = 0.f;
#pragma unroll
        for (int p = 0; p < NPART; p++) s += g_rnpart[(long long)p * (BATCH * 384) + row];
        float v = 1.f / fmaxf(sqrtf(s), 1e-12f);
        if (isK) srn_k[cc] = v; else srn_q[cc] = v;
    }
    __syncthreads();
    for (int i = tid; i < DHEAD * DHEAD; i += 256) {
        float s = 0.f;
        for (int p = 0; p < 16; p++)
            s += g_Apart[((long long)bh * 16 + p) * (DHEAD * DHEAD) + i];
        int c = i / DHEAD, d = i % DHEAD;
        sA[i] = s * srn_q[c] * srn_k[d] * temp[h];
    }
    __syncthreads();
    if (tid < DHEAD) {
        float mx = -1e30f;
        for (int d = 0; d < DHEAD; d++) mx = fmaxf(mx, sA[tid * DHEAD + d]);
        float sum = 0.f;
        for (int d = 0; d < DHEAD; d++) sum += __expf(sA[tid * DHEAD + d] - mx);
        float inv = 1.f / sum;
        for (int d = 0; d < DHEAD; d++)
            g_A[bh * DHEAD * DHEAD + tid * DHEAD + d] =
                __expf(sA[tid * DHEAD + d] - mx) * inv;
    }
}

// ---------------- out = A @ V via tensor cores ----------------------------------
__global__ __launch_bounds__(256) void av_kernel() {
    __shared__ __align__(16) __half Ab[48][56];
    __shared__ __align__(16) __half Vs[48][264];
    int bh = blockIdx.y;
    int b = bh >> 2, h = bh & 3;
    int tid = threadIdx.x, lane = tid & 31, wn = tid >> 5;
    int ra = lane >> 2, ca = lane & 3;
    int n0 = blockIdx.x * 256;

    for (int i = tid; i < DHEAD * DHEAD; i += 256)
        Ab[i / DHEAD][i % DHEAD] = __float2half(g_A[bh * DHEAD * DHEAD + i]);

    const __half* vb = g_S1h + ((long long)b * 576 + 2 * DIM + h * DHEAD) * HW;
#pragma unroll
    for (int i = 0; i < 6; i++) {
        int id = tid + i * 256;
        int d = id >> 5, c8 = (id & 31) * 8;
        cpa16(sm_addr(&Vs[d][c8]), &vb[(long long)d * HW + n0 + c8]);
    }
    cpa_commit();
    cpa_wait<0>();
    __syncthreads();

    float acc[3][4][4];
#pragma unroll
    for (int i = 0; i < 3; i++)
#pragma unroll
        for (int j = 0; j < 4; j++)
#pragma unroll
            for (int q = 0; q < 4; q++) acc[i][j][q] = 0.f;

#pragma unroll
    for (int ks = 0; ks < 3; ks++) {
        uint32_t afr[3][4], bfr[4][2];
#pragma unroll
        for (int mt = 0; mt < 3; mt++)
            ldsm_x4(afr[mt], sm_addr(&Ab[mt * 16 + (lane & 15)][ks * 16 + (lane >> 4) * 8]));
#pragma unroll
        for (int tnp = 0; tnp < 2; tnp++) {
            uint32_t t4[4];
            ldsm_x4t(t4, sm_addr(&Vs[ks * 16 + (lane & 15)]
                                    [wn * 32 + tnp * 16 + (lane >> 4) * 8]));
            bfr[2 * tnp][0] = t4[0]; bfr[2 * tnp][1] = t4[1];
            bfr[2 * tnp + 1][0] = t4[2]; bfr[2 * tnp + 1][1] = t4[3];
        }
#pragma unroll
        for (int mt = 0; mt < 3; mt++)
#pragma unroll
            for (int tn = 0; tn < 4; tn++)
                mma_f32acc(acc[mt][tn], afr[mt], bfr[tn]);
    }

    __half* ob = g_S2h + ((long long)b * DIM + h * DHEAD) * HW;
#pragma unroll
    for (int mt = 0; mt < 3; mt++)
#pragma unroll
        for (int tn = 0; tn < 4; tn++) {
            int col = n0 + wn * 32 + tn * 8 + 2 * ca;
            int c0 = mt * 16 + ra;
            *(uint32_t*)&ob[(long long)c0 * HW + col] =
                pack_h2(acc[mt][tn][0], acc[mt][tn][1]);
            *(uint32_t*)&ob[(long long)(c0 + 8) * HW + col] =
                pack_h2(acc[mt][tn][2], acc[mt][tn][3]);
        }
}

// ---------------- fused GDFN dw3x3 + GELU gate: vectorized 16-row tiles ---------
__global__ __launch_bounds__(256) void dw_gate_kernel(const __half* __restrict__ in,
                                                      const float* __restrict__ w9,
                                                      __half* __restrict__ out) {
    __shared__ __half st1[18][136], st2[18][136];
    int c = blockIdx.y, b = blockIdx.z;
    int y0 = blockIdx.x * 16;
    int tid = threadIdx.x;
    int r = tid >> 4, x0 = (tid & 15) * 8;
    long long obase = ((long long)b * 512 + c) * HW;

    if (c >= HIDDEN) {
        uint4 z = make_uint4(0u, 0u, 0u, 0u);
        *(uint4*)&out[obase + (y0 + r) * IMG_W + x0] = z;
        return;
    }
    long long base1 = ((long long)b * 1020 + c) * HW;
    long long base2 = ((long long)b * 1020 + HIDDEN + c) * HW;
    float w1[9], w2[9];
#pragma unroll
    for (int i = 0; i < 9; i++) { w1[i] = w9[c * 9 + i]; w2[i] = w9[(HIDDEN + c) * 9 + i]; }

    for (int id = tid; id < 288; id += 256) {
        int rr = id >> 4, c8 = (id & 15) * 8;
        int gy = y0 - 1 + rr;
        uint4 v1 = make_uint4(0u, 0u, 0u, 0u), v2 = v1;
        if ((unsigned)gy < IMG_W) {
            v1 = *(const uint4*)&in[base1 + gy * IMG_W + c8];
            v2 = *(const uint4*)&in[base2 + gy * IMG_W + c8];
        }
        *(uint4*)&st1[rr][c8] = v1;
        *(uint4*)&st2[rr][c8] = v2;
    }
    __syncthreads();

    float o1[8] = {}, o2[8] = {};
#pragma unroll
    for (int ky = 0; ky < 3; ky++) {
        float t1[10], t2[10];
#pragma unroll
        for (int i = 0; i < 10; i++) {
            int xx = x0 - 1 + i;
            bool ok = (unsigned)xx < IMG_W;
            t1[i] = ok ? __half2float(st1[r + ky][xx]) : 0.f;
            t2[i] = ok ? __half2float(st2[r + ky][xx]) : 0.f;
        }
        float a0 = w1[ky * 3], a1 = w1[ky * 3 + 1], a2 = w1[ky * 3 + 2];
        float b0 = w2[ky * 3], b1 = w2[ky * 3 + 1], b2 = w2[ky * 3 + 2];
#pragma unroll
        for (int j = 0; j < 8; j++) {
            o1[j] += a0 * t1[j] + a1 * t1[j + 1] + a2 * t1[j + 2];
            o2[j] += b0 * t2[j] + b1 * t2[j + 1] + b2 * t2[j + 2];
        }
    }
    uint4 pv;
    uint32_t* pp = (uint32_t*)&pv;
#pragma unroll
    for (int i = 0; i < 4; i++) {
        float g0 = 0.5f * o1[2 * i] * (1.f + erff(o1[2 * i] * 0.70710678118654752f));
        float g1 = 0.5f * o1[2 * i + 1] * (1.f + erff(o1[2 * i + 1] * 0.70710678118654752f));
        pp[i] = pack_h2(g0 * o2[2 * i], g1 * o2[2 * i + 1]);
    }
    *(uint4*)&out[obase + (y0 + r) * IMG_W + x0] = pv;
}

// =============================================================================
extern "C" void kernel_launch(void* const* d_in, const int* in_sizes, int n_in,
                              void* d_out, int out_size) {
    const float* x     = (const float*)d_in[0];
    const float* n1w   = (const float*)d_in[1];
    const float* qkvw  = (const float*)d_in[2];
    const float* qkvdw = (const float*)d_in[3];
    const float* temp  = (const float*)d_in[4];
    const float* projw = (const float*)d_in[5];
    const float* n2w   = (const float*)d_in[6];
    const float* pinw  = (const float*)d_in[7];
    const float* dww   = (const float*)d_in[8];
    const float* poutw = (const float*)d_in[9];
    float* out = (float*)d_out;

    __half *S0h, *S1h, *S2h, *Wqkv, *Wproj, *Wpin, *Wpout;
    cudaGetSymbolAddress((void**)&S0h, g_S0h);
    cudaGetSymbolAddress((void**)&S1h, g_S1h);
    cudaGetSymbolAddress((void**)&S2h, g_S2h);
    cudaGetSymbolAddress((void**)&Wqkv, g_Wqkv);
    cudaGetSymbolAddress((void**)&Wproj, g_Wproj);
    cudaGetSymbolAddress((void**)&Wpin, g_Wpin);
    cudaGetSymbolAddress((void**)&Wpout, g_Wpout);

    cudaFuncSetAttribute(gemm_fp16, cudaFuncAttributeMaxDynamicSharedMemorySize, GSMEM);

    dim3 pxGrid(HW / 256, BATCH);

    // ---- MDTA branch (qkv GEMM kept in ncu's capture slot: 4th launch) ----
    wconv_kernel<<<(640 * 192 + 255) / 256, 256>>>(qkvw, Wqkv, 576, 192, 640, 192);
    wconv_kernel<<<(256 * 192 + 255) / 256, 256>>>(projw, Wproj, 192, 192, 256, 192);
    ln_apply_kernel<<<pxGrid, 256>>>(x, n1w, S2h);

    // qkv 1x1: 576x192 (padded 640) -> fp16
    gemm_fp16<<<dim3(HW / 256, 5, BATCH), 256, GSMEM>>>(
        Wqkv, S2h, S0h, nullptr, 576, 192, (long long)DIM * HW, (long long)576 * HW, 1, 0);

    dw_qkv_kernel<<<dim3(NPART, 576, BATCH), 256>>>(S0h, qkvdw, S1h);
    attn_part_kernel<<<dim3(16, 16), 256>>>();
    attn_finish_kernel<<<16, 256>>>(temp);
    av_kernel<<<dim3(HW / 256, 16), 256>>>();

    // proj 1x1 (192x192, padded 256): fp16 -> fp32 + residual(x)
    gemm_fp16<<<dim3(HW / 256, 2, BATCH), 256, GSMEM>>>(
        Wproj, S2h, out, x, 192, 192, (long long)DIM * HW, (long long)DIM * HW, 0, 1);

    // ---- GDFN branch ----
    wconv_kernel<<<(1024 * 192 + 255) / 256, 256>>>(pinw, Wpin, 1020, 192, 1024, 192);
    wconv_kernel<<<(256 * 512 + 255) / 256, 256>>>(poutw, Wpout, 192, 510, 256, 512);
    ln_apply_kernel<<<pxGrid, 256>>>(out, n2w, S2h);

    // pin 1x1 (1020x192 padded 1024): fp16 -> fp16
    gemm_fp16<<<dim3(HW / 256, 8, BATCH), 256, GSMEM>>>(
        Wpin, S2h, S0h, nullptr, 1020, 192, (long long)DIM * HW, (long long)1020 * HW, 1, 0);

    dw_gate_kernel<<<dim3(NPART, 512, BATCH), 256>>>(S0h, dww, S1h);

    // pout 1x1 (192x512 padded 256): fp16 -> fp32 + residual(d_out)
    gemm_fp16<<<dim3(HW / 256, 2, BATCH), 256, GSMEM>>>(
        Wpout, S1h, out, out, 192, 512, (long long)512 * HW, (long long)DIM * HW, 0, 1);
}

// round 15
// speedup vs baseline: 1.6523x; 1.0040x over previous
#include <cuda_runtime.h>
#include <cuda_fp16.h>
#include <math.h>
#include <stdint.h>

#define HW 16384
#define IMG_W 128
#define DIM 192
#define HEADS 4
#define DHEAD 48
#define HIDDEN 510
#define BATCH 4
#define NPART 8

// ---------------- scratch (static device arrays) --------------------------------
__device__ __half g_S0h[BATCH * 1020 * HW]; // conv1x1 outputs (qkv:576 / pin:1020)
__device__ __half g_S1h[BATCH * 576 * HW];  // dw qkv out (576) / gated gdfn (512 pad)
__device__ __half g_S2h[BATCH * DIM * HW];  // LN-normalized xhat / attn output
__device__ __half g_Wqkv[640 * 192];        // padded 576->640
__device__ __half g_Wproj[256 * 192];       // padded 192->256
__device__ __half g_Wpin[1024 * 192];       // padded 1020->1024
__device__ __half g_Wpout[256 * 512];       // padded 192->256, K 510->512
__device__ float g_rnpart[NPART * BATCH * 2 * DIM]; // [p][r]
__device__ float g_A[16 * DHEAD * DHEAD];
__device__ float g_Apart[16 * 16 * DHEAD * DHEAD];

// ---------------- helpers -------------------------------------------------------
__device__ __forceinline__ uint32_t pack_h2(float x, float y) {
    __half2 h = __floats2half2_rn(x, y);
    return *(uint32_t*)&h;
}
__device__ __forceinline__ uint32_t sm_addr(const void* p) {
    return (uint32_t)__cvta_generic_to_shared(p);
}
__device__ __forceinline__ void ldsm_x4(uint32_t* r, uint32_t addr) {
    asm volatile("ldmatrix.sync.aligned.m8n8.x4.shared.b16 {%0,%1,%2,%3}, [%4];"
        : "=r"(r[0]), "=r"(r[1]), "=r"(r[2]), "=r"(r[3]) : "r"(addr));
}
__device__ __forceinline__ void ldsm_x4t(uint32_t* r, uint32_t addr) {
    asm volatile("ldmatrix.sync.aligned.m8n8.x4.trans.shared.b16 {%0,%1,%2,%3}, [%4];"
        : "=r"(r[0]), "=r"(r[1]), "=r"(r[2]), "=r"(r[3]) : "r"(addr));
}
__device__ __forceinline__ void ldsm_x2(uint32_t* r, uint32_t addr) {
    asm volatile("ldmatrix.sync.aligned.m8n8.x2.shared.b16 {%0,%1}, [%2];"
        : "=r"(r[0]), "=r"(r[1]) : "r"(addr));
}
__device__ __forceinline__ void mma_f16acc(uint32_t* d, const uint32_t* a, const uint32_t* b) {
    asm volatile("mma.sync.aligned.m16n8k16.row.col.f16.f16.f16.f16 "
        "{%0,%1}, {%2,%3,%4,%5}, {%6,%7}, {%0,%1};"
        : "+r"(d[0]), "+r"(d[1])
        : "r"(a[0]), "r"(a[1]), "r"(a[2]), "r"(a[3]), "r"(b[0]), "r"(b[1]));
}
__device__ __forceinline__ void mma_f32acc(float* d, const uint32_t* a, const uint32_t* b) {
    asm volatile("mma.sync.aligned.m16n8k16.row.col.f32.f16.f16.f32 "
        "{%0,%1,%2,%3}, {%4,%5,%6,%7}, {%8,%9}, {%0,%1,%2,%3};"
        : "+f"(d[0]), "+f"(d[1]), "+f"(d[2]), "+f"(d[3])
        : "r"(a[0]), "r"(a[1]), "r"(a[2]), "r"(a[3]), "r"(b[0]), "r"(b[1]));
}
__device__ __forceinline__ void cpa16(uint32_t dst, const void* src) {
    asm volatile("cp.async.cg.shared.global [%0], [%1], 16;" :: "r"(dst), "l"(src));
}
__device__ __forceinline__ void cpa_commit() { asm volatile("cp.async.commit_group;"); }
template<int N> __device__ __forceinline__ void cpa_wait() {
    asm volatile("cp.async.wait_group %0;" :: "n"(N));
}

// ---------------- weight fp32 -> fp16 with padding ------------------------------
__global__ __launch_bounds__(256) void wconv_kernel(const float* __restrict__ src,
                                                    __half* __restrict__ dst,
                                                    int M, int K, int Mp, int Kp) {
    int idx = blockIdx.x * 256 + threadIdx.x;
    int tot = Mp * Kp;
    if (idx >= tot) return;
    int m = idx / Kp, k = idx - m * Kp;
    float v = (m < M && k < K) ? src[m * K + k] : 0.f;
    dst[idx] = __float2half(v);
}

// ---------------- LN v2: single global read, channels held in registers --------
__global__ __launch_bounds__(256) void ln_apply_kernel(const float* __restrict__ x,
                                                       const float* __restrict__ lnW,
                                                       __half* __restrict__ xh) {
    __shared__ float sw[DIM];
    int tid = threadIdx.x;
    if (tid < DIM) sw[tid] = lnW[tid];
    __syncthreads();
    int n = blockIdx.x * 256 + tid;
    int b = blockIdx.y;
    const float* xb = x + (long long)b * DIM * HW + n;
    __half2 hv[96];
    float s = 0.f, s2 = 0.f;
#pragma unroll
    for (int i = 0; i < 96; i++) {
        float v0 = xb[(long long)(2 * i) * HW];
        float v1 = xb[(long long)(2 * i + 1) * HW];
        s += v0 + v1;
        s2 += v0 * v0 + v1 * v1;
        hv[i] = __floats2half2_rn(v0, v1);
    }
    float m = s * (1.f / DIM);
    float var = s2 * (1.f / DIM) - m * m;
    float inv = rsqrtf(var + 1e-6f);
    __half* ob = xh + (long long)b * DIM * HW + n;
#pragma unroll
    for (int i = 0; i < 96; i++) {
        float2 f = __half22float2(hv[i]);
        ob[(long long)(2 * i) * HW]     = __float2half((f.x - m) * inv * sw[2 * i]);
        ob[(long long)(2 * i + 1) * HW] = __float2half((f.y - m) * inv * sw[2 * i + 1]);
    }
}

// ---------------- fp16 GEMM: BM=128, BN=256, BK=32, fp16 accum, 3-stage ---------
#define ASTR 40
#define BSTR 264
#define ABYTES (128 * ASTR * 2)
#define BBYTES (32 * BSTR * 2)
#define NSTG 3
#define GSMEM (NSTG * (ABYTES + BBYTES))

__global__ __launch_bounds__(256) void gemm_fp16(const __half* __restrict__ Wb,
                                                 const __half* __restrict__ X,
                                                 void* __restrict__ Outv,
                                                 const float* __restrict__ Res,
                                                 int M, int K,
                                                 long long xbs, long long obs,
                                                 int outF16, int addRes) {
    extern __shared__ __align__(16) uint8_t dynsm[];
    uint32_t aBase = sm_addr(dynsm);
    uint32_t bBase = aBase + NSTG * ABYTES;
    int tid = threadIdx.x, lane = tid & 31, wid = tid >> 5;
    int wm = wid & 1, wn = wid >> 1;       // 2(M) x 4(N)
    int ra = lane >> 2, ca = lane & 3;
    int n0 = blockIdx.x * 256;
    int m0 = blockIdx.y * 128;
    int b  = blockIdx.z;
    const __half* Xb = X + (long long)b * xbs;

    uint32_t acc[4][8][2];
#pragma unroll
    for (int i = 0; i < 4; i++)
#pragma unroll
        for (int j = 0; j < 8; j++) { acc[i][j][0] = 0u; acc[i][j][1] = 0u; }

    int nk = K >> 5;

    auto load_slab = [&](int kt, int s) {
        int kb = kt << 5;
        uint32_t aS = aBase + s * ABYTES;
        uint32_t bS = bBase + s * BBYTES;
#pragma unroll
        for (int i = 0; i < 2; i++) {
            int id = tid + i * 256;
            int m = id >> 2, kc = (id & 3) * 8;
            cpa16(aS + (uint32_t)(m * ASTR + kc) * 2,
                  &Wb[(long long)(m0 + m) * K + kb + kc]);
        }
#pragma unroll
        for (int i = 0; i < 4; i++) {
            int id = tid + i * 256;
            int kr = id >> 5, nc = (id & 31) * 8;
            cpa16(bS + (uint32_t)(kr * BSTR + nc) * 2,
                  &Xb[(long long)(kb + kr) * HW + n0 + nc]);
        }
    };

    load_slab(0, 0); cpa_commit();
    if (nk > 1) load_slab(1, 1);
    cpa_commit();

    for (int kt = 0; kt < nk; kt++) {
        cpa_wait<1>();
        __syncthreads();
        if (kt + 2 < nk) load_slab(kt + 2, (kt + 2) % NSTG);
        cpa_commit();
        int s = kt % NSTG;
        uint32_t aS = aBase + s * ABYTES;
        uint32_t bS = bBase + s * BBYTES;
#pragma unroll
        for (int ks = 0; ks < 2; ks++) {
            uint32_t afr[4][4], bfr[8][2];
#pragma unroll
            for (int tm = 0; tm < 4; tm++)
                ldsm_x4(afr[tm], aS + (uint32_t)((wm * 64 + tm * 16 + (lane & 15)) * ASTR
                                                 + ks * 16 + (lane >> 4) * 8) * 2);
#pragma unroll
            for (int tnp = 0; tnp < 4; tnp++) {
                uint32_t t4[4];
                ldsm_x4t(t4, bS + (uint32_t)((ks * 16 + (lane & 15)) * BSTR
                                             + wn * 64 + tnp * 16 + (lane >> 4) * 8) * 2);
                bfr[2 * tnp][0] = t4[0]; bfr[2 * tnp][1] = t4[1];
                bfr[2 * tnp + 1][0] = t4[2]; bfr[2 * tnp + 1][1] = t4[3];
            }
#pragma unroll
            for (int tm = 0; tm < 4; tm++)
#pragma unroll
                for (int tn = 0; tn < 8; tn++)
                    mma_f16acc(acc[tm][tn], afr[tm], bfr[tn]);
        }
    }

    __syncthreads();
    if (outF16) {
        __half* Ob = (__half*)Outv + (long long)b * obs;
#pragma unroll
        for (int tm = 0; tm < 4; tm++)
#pragma unroll
            for (int tn = 0; tn < 8; tn++) {
                int col = n0 + wn * 64 + tn * 8 + 2 * ca;
                int r0 = m0 + wm * 64 + tm * 16 + ra;
                int r1 = r0 + 8;
                if (r0 < M) *(uint32_t*)&Ob[(long long)r0 * HW + col] = acc[tm][tn][0];
                if (r1 < M) *(uint32_t*)&Ob[(long long)r1 * HW + col] = acc[tm][tn][1];
            }
    } else {
        float* Ob = (float*)Outv + (long long)b * obs;
        const float* Rb = Res + (long long)b * obs;
#pragma unroll
        for (int tm = 0; tm < 4; tm++)
#pragma unroll
            for (int tn = 0; tn < 8; tn++) {
                int col = n0 + wn * 64 + tn * 8 + 2 * ca;
                int r0 = m0 + wm * 64 + tm * 16 + ra;
                int r1 = r0 + 8;
                if (r0 < M) {
                    float2 v = __half22float2(*(__half2*)&acc[tm][tn][0]);
                    long long off = (long long)r0 * HW + col;
                    if (addRes) { float2 rr = *(const float2*)&Rb[off]; v.x += rr.x; v.y += rr.y; }
                    *(float2*)&Ob[off] = v;
                }
                if (r1 < M) {
                    float2 v = __half22float2(*(__half2*)&acc[tm][tn][1]);
                    long long off = (long long)r1 * HW + col;
                    if (addRes) { float2 rr = *(const float2*)&Rb[off]; v.x += rr.x; v.y += rr.y; }
                    *(float2*)&Ob[off] = v;
                }
            }
    }
}

// ---------------- depthwise 3x3 qkv: vectorized 16-row tiles --------------------
__global__ __launch_bounds__(256) void dw_qkv_kernel(const __half* __restrict__ in,
                                                     const float* __restrict__ w9,
                                                     __half* __restrict__ out) {
    __shared__ __half st[18][136];
    __shared__ float red[256];
    int c = blockIdx.y, b = blockIdx.z;
    long long base = ((long long)b * 576 + c) * HW;
    const __half* ib = in + base;
    int y0 = blockIdx.x * 16;
    int tid = threadIdx.x;
    float w[9];
#pragma unroll
    for (int i = 0; i < 9; i++) w[i] = w9[c * 9 + i];

    for (int id = tid; id < 288; id += 256) {
        int r = id >> 4, c8 = (id & 15) * 8;
        int gy = y0 - 1 + r;
        uint4 v = make_uint4(0u, 0u, 0u, 0u);
        if ((unsigned)gy < IMG_W) v = *(const uint4*)&ib[gy * IMG_W + c8];
        *(uint4*)&st[r][c8] = v;
    }
    __syncthreads();

    int r = tid >> 4, x0 = (tid & 15) * 8;
    float o[8] = {};
#pragma unroll
    for (int ky = 0; ky < 3; ky++) {
        float t[10];
#pragma unroll
        for (int i = 0; i < 10; i++) {
            int xx = x0 - 1 + i;
            t[i] = ((unsigned)xx < IMG_W) ? __half2float(st[r + ky][xx]) : 0.f;
        }
        float w0 = w[ky * 3], w1 = w[ky * 3 + 1], w2 = w[ky * 3 + 2];
#pragma unroll
        for (int j = 0; j < 8; j++)
            o[j] += w0 * t[j] + w1 * t[j + 1] + w2 * t[j + 2];
    }
    uint4 pv;
    uint32_t* pp = (uint32_t*)&pv;
#pragma unroll
    for (int i = 0; i < 4; i++) pp[i] = pack_h2(o[2 * i], o[2 * i + 1]);
    *(uint4*)&out[base + (y0 + r) * IMG_W + x0] = pv;

    if (c < 384) {
        float ss = 0.f;
#pragma unroll
        for (int j = 0; j < 8; j++) ss += o[j] * o[j];
        red[tid] = ss;
        __syncthreads();
        for (int stp = 128; stp; stp >>= 1) {
            if (tid < stp) red[tid] += red[tid + stp];
            __syncthreads();
        }
        if (tid == 0)
            g_rnpart[(long long)blockIdx.x * (BATCH * 384) + b * 384 + c] = red[0];
    }
}

// ---------------- split-K partial Q.K^T via tensor cores ------------------------
__global__ __launch_bounds__(256) void attn_part_kernel() {
    __shared__ __align__(16) __half Qs[48][72];
    __shared__ __align__(16) __half Ks[48][72];
    int chunk = blockIdx.x;
    int bh = blockIdx.y;
    int b = bh >> 2, h = bh & 3;
    const __half* qb = g_S1h + ((long long)b * 576 + h * DHEAD) * HW;
    const __half* kb = g_S1h + ((long long)b * 576 + DIM + h * DHEAD) * HW;
    int tid = threadIdx.x, lane = tid & 31, w = tid >> 5;
    int mt = w >> 1, nh = w & 1;
    int ra = lane >> 2, ca = lane & 3;
    long long nbase = (long long)chunk * 1024;

    float acc[3][4] = {};

    for (int sl = 0; sl < 16; sl++) {
        long long nb = nbase + sl * 64;
#pragma unroll
        for (int i = 0; i < 3; i++) {
            int id = tid + i * 256;
            int r = id >> 3;
            int c8 = (id & 7) * 8;
            if (r < 48)
                cpa16(sm_addr(&Qs[r][c8]), &qb[(long long)r * HW + nb + c8]);
            else
                cpa16(sm_addr(&Ks[r - 48][c8]), &kb[(long long)(r - 48) * HW + nb + c8]);
        }
        cpa_commit();
        cpa_wait<0>();
        __syncthreads();
        if (w < 6) {
#pragma unroll
            for (int kp = 0; kp < 4; kp++) {
                uint32_t afr[4], bfr[3][2];
                ldsm_x4(afr, sm_addr(&Qs[mt * 16 + (lane & 15)][kp * 16 + (lane >> 4) * 8]));
#pragma unroll
                for (int tn = 0; tn < 3; tn++)
                    ldsm_x2(bfr[tn], sm_addr(&Ks[nh * 24 + tn * 8 + (lane & 7)]
                                                [kp * 16 + ((lane >> 3) & 1) * 8]));
#pragma unroll
                for (int tn = 0; tn < 3; tn++)
                    mma_f32acc(acc[tn], afr, bfr[tn]);
            }
        }
        __syncthreads();
    }
    if (w < 6) {
        float* P = g_Apart + ((long long)bh * 16 + chunk) * (DHEAD * DHEAD);
#pragma unroll
        for (int tn = 0; tn < 3; tn++) {
            int d0 = nh * 24 + tn * 8 + 2 * ca;
            int c0 = mt * 16 + ra;
            *(float2*)&P[c0 * DHEAD + d0] = make_float2(acc[tn][0], acc[tn][1]);
            *(float2*)&P[(c0 + 8) * DHEAD + d0] = make_float2(acc[tn][2], acc[tn][3]);
        }
    }
}

// ---------------- reduce partials + rownorms, scale, softmax --------------------
__global__ __launch_bounds__(256) void attn_finish_kernel(const float* __restrict__ temp) {
    int bh = blockIdx.x;
    int b = bh >> 2, h = bh & 3;
    __shared__ float sA[DHEAD * DHEAD];
    __shared__ float srn_q[DHEAD], srn_k[DHEAD];
    int tid = threadIdx.x;
    if (tid < 96) {
        int i = tid;
        int isK = (i >= DHEAD);
        int cc = i - isK * DHEAD;
        int row = b * 384 + isK * DIM + h * DHEAD + cc;
        float s = 0.f;
#pragma unroll
        for (int p = 0; p < NPART; p++) s += g_rnpart[(long long)p * (BATCH * 384) + row];
        float v = 1.f / fmaxf(sqrtf(s), 1e-12f);
        if (isK) srn_k[cc] = v; else srn_q[cc] = v;
    }
    __syncthreads();
    for (int i = tid; i < DHEAD * DHEAD; i += 256) {
        float s = 0.f;
        for (int p = 0; p < 16; p++)
            s += g_Apart[((long long)bh * 16 + p) * (DHEAD * DHEAD) + i];
        int c = i / DHEAD, d = i % DHEAD;
        sA[i] = s * srn_q[c] * srn_k[d] * temp[h];
    }
    __syncthreads();
    if (tid < DHEAD) {
        float mx = -1e30f;
        for (int d = 0; d < DHEAD; d++) mx = fmaxf(mx, sA[tid * DHEAD + d]);
        float sum = 0.f;
        for (int d = 0; d < DHEAD; d++) sum += __expf(sA[tid * DHEAD + d] - mx);
        float inv = 1.f / sum;
        for (int d = 0; d < DHEAD; d++)
            g_A[bh * DHEAD * DHEAD + tid * DHEAD + d] =
                __expf(sA[tid * DHEAD + d] - mx) * inv;
    }
}

// ---------------- out = A @ V via tensor cores ----------------------------------
__global__ __launch_bounds__(256) void av_kernel() {
    __shared__ __align__(16) __half Ab[48][56];
    __shared__ __align__(16) __half Vs[48][264];
    int bh = blockIdx.y;
    int b = bh >> 2, h = bh & 3;
    int tid = threadIdx.x, lane = tid & 31, wn = tid >> 5;
    int ra = lane >> 2, ca = lane & 3;
    int n0 = blockIdx.x * 256;

    for (int i = tid; i < DHEAD * DHEAD; i += 256)
        Ab[i / DHEAD][i % DHEAD] = __float2half(g_A[bh * DHEAD * DHEAD + i]);

    const __half* vb = g_S1h + ((long long)b * 576 + 2 * DIM + h * DHEAD) * HW;
#pragma unroll
    for (int i = 0; i < 6; i++) {
        int id = tid + i * 256;
        int d = id >> 5, c8 = (id & 31) * 8;
        cpa16(sm_addr(&Vs[d][c8]), &vb[(long long)d * HW + n0 + c8]);
    }
    cpa_commit();
    cpa_wait<0>();
    __syncthreads();

    float acc[3][4][4];
#pragma unroll
    for (int i = 0; i < 3; i++)
#pragma unroll
        for (int j = 0; j < 4; j++)
#pragma unroll
            for (int q = 0; q < 4; q++) acc[i][j][q] = 0.f;

#pragma unroll
    for (int ks = 0; ks < 3; ks++) {
        uint32_t afr[3][4], bfr[4][2];
#pragma unroll
        for (int mt = 0; mt < 3; mt++)
            ldsm_x4(afr[mt], sm_addr(&Ab[mt * 16 + (lane & 15)][ks * 16 + (lane >> 4) * 8]));
#pragma unroll
        for (int tnp = 0; tnp < 2; tnp++) {
            uint32_t t4[4];
            ldsm_x4t(t4, sm_addr(&Vs[ks * 16 + (lane & 15)]
                                    [wn * 32 + tnp * 16 + (lane >> 4) * 8]));
            bfr[2 * tnp][0] = t4[0]; bfr[2 * tnp][1] = t4[1];
            bfr[2 * tnp + 1][0] = t4[2]; bfr[2 * tnp + 1][1] = t4[3];
        }
#pragma unroll
        for (int mt = 0; mt < 3; mt++)
#pragma unroll
            for (int tn = 0; tn < 4; tn++)
                mma_f32acc(acc[mt][tn], afr[mt], bfr[tn]);
    }

    __half* ob = g_S2h + ((long long)b * DIM + h * DHEAD) * HW;
#pragma unroll
    for (int mt = 0; mt < 3; mt++)
#pragma unroll
        for (int tn = 0; tn < 4; tn++) {
            int col = n0 + wn * 32 + tn * 8 + 2 * ca;
            int c0 = mt * 16 + ra;
            *(uint32_t*)&ob[(long long)c0 * HW + col] =
                pack_h2(acc[mt][tn][0], acc[mt][tn][1]);
            *(uint32_t*)&ob[(long long)(c0 + 8) * HW + col] =
                pack_h2(acc[mt][tn][2], acc[mt][tn][3]);
        }
}

// ---------------- fused GDFN dw3x3 + GELU gate: vectorized 16-row tiles ---------
__global__ __launch_bounds__(256) void dw_gate_kernel(const __half* __restrict__ in,
                                                      const float* __restrict__ w9,
                                                      __half* __restrict__ out) {
    __shared__ __half st1[18][136], st2[18][136];
    int c = blockIdx.y, b = blockIdx.z;
    int y0 = blockIdx.x * 16;
    int tid = threadIdx.x;
    int r = tid >> 4, x0 = (tid & 15) * 8;
    long long obase = ((long long)b * 512 + c) * HW;

    if (c >= HIDDEN) {
        uint4 z = make_uint4(0u, 0u, 0u, 0u);
        *(uint4*)&out[obase + (y0 + r) * IMG_W + x0] = z;
        return;
    }
    long long base1 = ((long long)b * 1020 + c) * HW;
    long long base2 = ((long long)b * 1020 + HIDDEN + c) * HW;
    float w1[9], w2[9];
#pragma unroll
    for (int i = 0; i < 9; i++) { w1[i] = w9[c * 9 + i]; w2[i] = w9[(HIDDEN + c) * 9 + i]; }

    for (int id = tid; id < 288; id += 256) {
        int rr = id >> 4, c8 = (id & 15) * 8;
        int gy = y0 - 1 + rr;
        uint4 v1 = make_uint4(0u, 0u, 0u, 0u), v2 = v1;
        if ((unsigned)gy < IMG_W) {
            v1 = *(const uint4*)&in[base1 + gy * IMG_W + c8];
            v2 = *(const uint4*)&in[base2 + gy * IMG_W + c8];
        }
        *(uint4*)&st1[rr][c8] = v1;
        *(uint4*)&st2[rr][c8] = v2;
    }
    __syncthreads();

    float o1[8] = {}, o2[8] = {};
#pragma unroll
    for (int ky = 0; ky < 3; ky++) {
        float t1[10], t2[10];
#pragma unroll
        for (int i = 0; i < 10; i++) {
            int xx = x0 - 1 + i;
            bool ok = (unsigned)xx < IMG_W;
            t1[i] = ok ? __half2float(st1[r + ky][xx]) : 0.f;
            t2[i] = ok ? __half2float(st2[r + ky][xx]) : 0.f;
        }
        float a0 = w1[ky * 3], a1 = w1[ky * 3 + 1], a2 = w1[ky * 3 + 2];
        float b0 = w2[ky * 3], b1 = w2[ky * 3 + 1], b2 = w2[ky * 3 + 2];
#pragma unroll
        for (int j = 0; j < 8; j++) {
            o1[j] += a0 * t1[j] + a1 * t1[j + 1] + a2 * t1[j + 2];
            o2[j] += b0 * t2[j] + b1 * t2[j + 1] + b2 * t2[j + 2];
        }
    }
    uint4 pv;
    uint32_t* pp = (uint32_t*)&pv;
#pragma unroll
    for (int i = 0; i < 4; i++) {
        float g0 = 0.5f * o1[2 * i] * (1.f + erff(o1[2 * i] * 0.70710678118654752f));
        float g1 = 0.5f * o1[2 * i + 1] * (1.f + erff(o1[2 * i + 1] * 0.70710678118654752f));
        pp[i] = pack_h2(g0 * o2[2 * i], g1 * o2[2 * i + 1]);
    }
    *(uint4*)&out[obase + (y0 + r) * IMG_W + x0] = pv;
}

// =============================================================================
extern "C" void kernel_launch(void* const* d_in, const int* in_sizes, int n_in,
                              void* d_out, int out_size) {
    const float* x     = (const float*)d_in[0];
    const float* n1w   = (const float*)d_in[1];
    const float* qkvw  = (const float*)d_in[2];
    const float* qkvdw = (const float*)d_in[3];
    const float* temp  = (const float*)d_in[4];
    const float* projw = (const float*)d_in[5];
    const float* n2w   = (const float*)d_in[6];
    const float* pinw  = (const float*)d_in[7];
    const float* dww   = (const float*)d_in[8];
    const float* poutw = (const float*)d_in[9];
    float* out = (float*)d_out;

    __half *S0h, *S1h, *S2h, *Wqkv, *Wproj, *Wpin, *Wpout;
    cudaGetSymbolAddress((void**)&S0h, g_S0h);
    cudaGetSymbolAddress((void**)&S1h, g_S1h);
    cudaGetSymbolAddress((void**)&S2h, g_S2h);
    cudaGetSymbolAddress((void**)&Wqkv, g_Wqkv);
    cudaGetSymbolAddress((void**)&Wproj, g_Wproj);
    cudaGetSymbolAddress((void**)&Wpin, g_Wpin);
    cudaGetSymbolAddress((void**)&Wpout, g_Wpout);

    cudaFuncSetAttribute(gemm_fp16, cudaFuncAttributeMaxDynamicSharedMemorySize, GSMEM);

    dim3 pxGrid(HW / 256, BATCH);

    // ---- MDTA branch (qkv GEMM kept in ncu's capture slot: 4th launch) ----
    wconv_kernel<<<(640 * 192 + 255) / 256, 256>>>(qkvw, Wqkv, 576, 192, 640, 192);
    wconv_kernel<<<(256 * 192 + 255) / 256, 256>>>(projw, Wproj, 192, 192, 256, 192);
    ln_apply_kernel<<<pxGrid, 256>>>(x, n1w, S2h);

    // qkv 1x1: 576x192 (padded 640) -> fp16
    gemm_fp16<<<dim3(HW / 256, 5, BATCH), 256, GSMEM>>>(
        Wqkv, S2h, S0h, nullptr, 576, 192, (long long)DIM * HW, (long long)576 * HW, 1, 0);

    dw_qkv_kernel<<<dim3(NPART, 576, BATCH), 256>>>(S0h, qkvdw, S1h);
    attn_part_kernel<<<dim3(16, 16), 256>>>();
    attn_finish_kernel<<<16, 256>>>(temp);
    av_kernel<<<dim3(HW / 256, 16), 256>>>();

    // proj 1x1 (192x192, padded 256): fp16 -> fp32 + residual(x)
    gemm_fp16<<<dim3(HW / 256, 2, BATCH), 256, GSMEM>>>(
        Wproj, S2h, out, x, 192, 192, (long long)DIM * HW, (long long)DIM * HW, 0, 1);

    // ---- GDFN branch ----
    wconv_kernel<<<(1024 * 192 + 255) / 256, 256>>>(pinw, Wpin, 1020, 192, 1024, 192);
    wconv_kernel<<<(256 * 512 + 255) / 256, 256>>>(poutw, Wpout, 192, 510, 256, 512);
    ln_apply_kernel<<<pxGrid, 256>>>(out, n2w, S2h);

    // pin 1x1 (1020x192 padded 1024): fp16 -> fp16
    gemm_fp16<<<dim3(HW / 256, 8, BATCH), 256, GSMEM>>>(
        Wpin, S2h, S0h, nullptr, 1020, 192, (long long)DIM * HW, (long long)1020 * HW, 1, 0);

    dw_gate_kernel<<<dim3(NPART, 512, BATCH), 256>>>(S0h, dww, S1h);

    // pout 1x1 (192x512 padded 256): fp16 -> fp32 + residual(d_out)
    gemm_fp16<<<dim3(HW / 256, 2, BATCH), 256, GSMEM>>>(
        Wpout, S1h, out, out, 192, 512, (long long)512 * HW, (long long)DIM * HW, 0, 1);
}

// round 16
// speedup vs baseline: 1.7042x; 1.0314x over previous
#include <cuda_runtime.h>
#include <cuda_fp16.h>
#include <math.h>
#include <stdint.h>

#define HW 16384
#define IMG_W 128
#define DIM 192
#define HEADS 4
#define DHEAD 48
#define HIDDEN 510
#define BATCH 4
#define NPART 8

// ---------------- scratch (static device arrays) --------------------------------
__device__ __half g_S0h[BATCH * 1020 * HW]; // conv1x1 outputs / ln2 fp16 source
__device__ __half g_S1h[BATCH * 576 * HW];  // dw qkv out (576) / gated gdfn (512 pad)
__device__ __half g_S2h[BATCH * DIM * HW];  // LN-normalized xhat / attn output
__device__ __half g_Wqkv[576 * 192];
__device__ __half g_Wproj[192 * 192];
__device__ __half g_Wpin[1024 * 192];       // padded 1020->1024
__device__ __half g_Wpout[192 * 512];       // padded K 510->512
__device__ float g_rnpart[NPART * BATCH * 2 * DIM]; // [p][r]
__device__ float g_A[16 * DHEAD * DHEAD];
__device__ float g_Apart[16 * 16 * DHEAD * DHEAD];

// ---------------- helpers -------------------------------------------------------
__device__ __forceinline__ uint32_t pack_h2(float x, float y) {
    __half2 h = __floats2half2_rn(x, y);
    return *(uint32_t*)&h;
}
__device__ __forceinline__ uint32_t sm_addr(const void* p) {
    return (uint32_t)__cvta_generic_to_shared(p);
}
__device__ __forceinline__ void ldsm_x4(uint32_t* r, uint32_t addr) {
    asm volatile("ldmatrix.sync.aligned.m8n8.x4.shared.b16 {%0,%1,%2,%3}, [%4];"
        : "=r"(r[0]), "=r"(r[1]), "=r"(r[2]), "=r"(r[3]) : "r"(addr));
}
__device__ __forceinline__ void ldsm_x4t(uint32_t* r, uint32_t addr) {
    asm volatile("ldmatrix.sync.aligned.m8n8.x4.trans.shared.b16 {%0,%1,%2,%3}, [%4];"
        : "=r"(r[0]), "=r"(r[1]), "=r"(r[2]), "=r"(r[3]) : "r"(addr));
}
__device__ __forceinline__ void ldsm_x2(uint32_t* r, uint32_t addr) {
    asm volatile("ldmatrix.sync.aligned.m8n8.x2.shared.b16 {%0,%1}, [%2];"
        : "=r"(r[0]), "=r"(r[1]) : "r"(addr));
}
__device__ __forceinline__ void mma_f16acc(uint32_t* d, const uint32_t* a, const uint32_t* b) {
    asm volatile("mma.sync.aligned.m16n8k16.row.col.f16.f16.f16.f16 "
        "{%0,%1}, {%2,%3,%4,%5}, {%6,%7}, {%0,%1};"
        : "+r"(d[0]), "+r"(d[1])
        : "r"(a[0]), "r"(a[1]), "r"(a[2]), "r"(a[3]), "r"(b[0]), "r"(b[1]));
}
__device__ __forceinline__ void mma_f32acc(float* d, const uint32_t* a, const uint32_t* b) {
    asm volatile("mma.sync.aligned.m16n8k16.row.col.f32.f16.f16.f32 "
        "{%0,%1,%2,%3}, {%4,%5,%6,%7}, {%8,%9}, {%0,%1,%2,%3};"
        : "+f"(d[0]), "+f"(d[1]), "+f"(d[2]), "+f"(d[3])
        : "r"(a[0]), "r"(a[1]), "r"(a[2]), "r"(a[3]), "r"(b[0]), "r"(b[1]));
}
__device__ __forceinline__ void cpa16(uint32_t dst, const void* src) {
    asm volatile("cp.async.cg.shared.global [%0], [%1], 16;" :: "r"(dst), "l"(src));
}
__device__ __forceinline__ void cpa_commit() { asm volatile("cp.async.commit_group;"); }
template<int N> __device__ __forceinline__ void cpa_wait() {
    asm volatile("cp.async.wait_group %0;" :: "n"(N));
}

// ---------------- weight fp32 -> fp16 with padding ------------------------------
__global__ __launch_bounds__(256) void wconv_kernel(const float* __restrict__ src,
                                                    __half* __restrict__ dst,
                                                    int M, int K, int Mp, int Kp) {
    int idx = blockIdx.x * 256 + threadIdx.x;
    int tot = Mp * Kp;
    if (idx >= tot) return;
    int m = idx / Kp, k = idx - m * Kp;
    float v = (m < M && k < K) ? src[m * K + k] : 0.f;
    dst[idx] = __float2half(v);
}

// ---------------- LN from fp32 input -------------------------------------------
__global__ __launch_bounds__(256) void ln_apply_kernel(const float* __restrict__ x,
                                                       const float* __restrict__ lnW,
                                                       __half* __restrict__ xh) {
    __shared__ float sw[DIM];
    int tid = threadIdx.x;
    if (tid < DIM) sw[tid] = lnW[tid];
    __syncthreads();
    int n = blockIdx.x * 256 + tid;
    int b = blockIdx.y;
    const float* xb = x + (long long)b * DIM * HW + n;
    float s = 0.f, s2 = 0.f;
#pragma unroll 8
    for (int c = 0; c < DIM; c++) {
        float v = xb[(long long)c * HW];
        s += v; s2 += v * v;
    }
    float m = s * (1.f / DIM);
    float var = s2 * (1.f / DIM) - m * m;
    float inv = rsqrtf(var + 1e-6f);
    __half* ob = xh + (long long)b * DIM * HW + n;
#pragma unroll 8
    for (int c = 0; c < DIM; c++)
        ob[(long long)c * HW] = __float2half((xb[(long long)c * HW] - m) * inv * sw[c]);
}

// ---------------- LN from fp16 input (ln2 path, reads proj's fp16 copy) ---------
__global__ __launch_bounds__(256) void ln_apply_h_kernel(const __half* __restrict__ x,
                                                         const float* __restrict__ lnW,
                                                         __half* __restrict__ xh) {
    __shared__ float sw[DIM];
    int tid = threadIdx.x;
    if (tid < DIM) sw[tid] = lnW[tid];
    __syncthreads();
    int n = blockIdx.x * 256 + tid;
    int b = blockIdx.y;
    const __half* xb = x + (long long)b * DIM * HW + n;
    float vv[DIM / 2];  // hold as pairs? keep simple: two-pass over fp16 (L2-hot)
    float s = 0.f, s2 = 0.f;
#pragma unroll 8
    for (int c = 0; c < DIM; c++) {
        float v = __half2float(xb[(long long)c * HW]);
        s += v; s2 += v * v;
        if (c & 1) vv[c >> 1] = v;       // store odd; even recomputed below
    }
    float m = s * (1.f / DIM);
    float var = s2 * (1.f / DIM) - m * m;
    float inv = rsqrtf(var + 1e-6f);
    __half* ob = xh + (long long)b * DIM * HW + n;
#pragma unroll 8
    for (int c = 0; c < DIM; c++) {
        float v = (c & 1) ? vv[c >> 1] : __half2float(xb[(long long)c * HW]);
        ob[(long long)c * HW] = __float2half((v - m) * inv * sw[c]);
    }
}

// ---------------- fp16 GEMM v5: BM=64, BN=256, BK=32, 128 thr, 4 CTAs/SM --------
#define ASTR 40
#define BSTR 264

__global__ __launch_bounds__(128, 4) void gemm_fp16(const __half* __restrict__ Wb,
                                                    const __half* __restrict__ X,
                                                    void* __restrict__ Outv,
                                                    const float* __restrict__ Res,
                                                    __half* __restrict__ OutCopy,
                                                    int M, int K,
                                                    long long xbs, long long obs,
                                                    int outF16, int addRes) {
    __shared__ __align__(16) __half As[2][64][ASTR];
    __shared__ __align__(16) __half Bs[2][32][BSTR];
    int tid = threadIdx.x, lane = tid & 31, wn = tid >> 5;   // 4 warps: wn = N slice
    int ra = lane >> 2, ca = lane & 3;
    int n0 = blockIdx.x * 256;
    int m0 = blockIdx.y * 64;
    int b  = blockIdx.z;
    const __half* Xb = X + (long long)b * xbs;

    uint32_t acc[4][8][2];
#pragma unroll
    for (int i = 0; i < 4; i++)
#pragma unroll
        for (int j = 0; j < 8; j++) { acc[i][j][0] = 0u; acc[i][j][1] = 0u; }

    int nk = K >> 5;

    auto load_slab = [&](int kt, int s) {
        int kb = kt << 5;
#pragma unroll
        for (int i = 0; i < 2; i++) {           // A: 256 chunks, 2/thread
            int id = tid + i * 128;
            int m = id >> 2, kc = (id & 3) * 8;
            cpa16(sm_addr(&As[s][m][kc]), &Wb[(long long)(m0 + m) * K + kb + kc]);
        }
#pragma unroll
        for (int i = 0; i < 8; i++) {           // B: 1024 chunks, 8/thread
            int id = tid + i * 128;
            int kr = id >> 5, nc = (id & 31) * 8;
            cpa16(sm_addr(&Bs[s][kr][nc]), &Xb[(long long)(kb + kr) * HW + n0 + nc]);
        }
    };

    load_slab(0, 0);
    cpa_commit();

    for (int kt = 0; kt < nk; kt++) {
        if (kt + 1 < nk) load_slab(kt + 1, (kt + 1) & 1);
        cpa_commit();
        cpa_wait<1>();
        __syncthreads();
        int s = kt & 1;
#pragma unroll
        for (int ks = 0; ks < 2; ks++) {
            uint32_t afr[4][4], bfr[8][2];
#pragma unroll
            for (int tm = 0; tm < 4; tm++)
                ldsm_x4(afr[tm], sm_addr(&As[s][tm * 16 + (lane & 15)]
                                            [ks * 16 + (lane >> 4) * 8]));
#pragma unroll
            for (int tnp = 0; tnp < 4; tnp++) {
                uint32_t t4[4];
                ldsm_x4t(t4, sm_addr(&Bs[s][ks * 16 + (lane & 15)]
                                        [wn * 64 + tnp * 16 + (lane >> 4) * 8]));
                bfr[2 * tnp][0] = t4[0]; bfr[2 * tnp][1] = t4[1];
                bfr[2 * tnp + 1][0] = t4[2]; bfr[2 * tnp + 1][1] = t4[3];
            }
#pragma unroll
            for (int tm = 0; tm < 4; tm++)
#pragma unroll
                for (int tn = 0; tn < 8; tn++)
                    mma_f16acc(acc[tm][tn], afr[tm], bfr[tn]);
        }
        __syncthreads();
    }

    if (outF16) {
        __half* Ob = (__half*)Outv + (long long)b * obs;
#pragma unroll
        for (int tm = 0; tm < 4; tm++)
#pragma unroll
            for (int tn = 0; tn < 8; tn++) {
                int col = n0 + wn * 64 + tn * 8 + 2 * ca;
                int r0 = m0 + tm * 16 + ra;
                int r1 = r0 + 8;
                if (r0 < M) *(uint32_t*)&Ob[(long long)r0 * HW + col] = acc[tm][tn][0];
                if (r1 < M) *(uint32_t*)&Ob[(long long)r1 * HW + col] = acc[tm][tn][1];
            }
    } else {
        float* Ob = (float*)Outv + (long long)b * obs;
        const float* Rb = Res + (long long)b * obs;
        __half* Cb = OutCopy ? OutCopy + (long long)b * obs : nullptr;
#pragma unroll
        for (int tm = 0; tm < 4; tm++)
#pragma unroll
            for (int tn = 0; tn < 8; tn++) {
                int col = n0 + wn * 64 + tn * 8 + 2 * ca;
                int r0 = m0 + tm * 16 + ra;
                int r1 = r0 + 8;
                if (r0 < M) {
                    float2 v = __half22float2(*(__half2*)&acc[tm][tn][0]);
                    long long off = (long long)r0 * HW + col;
                    if (addRes) { float2 rr = *(const float2*)&Rb[off]; v.x += rr.x; v.y += rr.y; }
                    *(float2*)&Ob[off] = v;
                    if (Cb) *(uint32_t*)&Cb[off] = pack_h2(v.x, v.y);
                }
                if (r1 < M) {
                    float2 v = __half22float2(*(__half2*)&acc[tm][tn][1]);
                    long long off = (long long)r1 * HW + col;
                    if (addRes) { float2 rr = *(const float2*)&Rb[off]; v.x += rr.x; v.y += rr.y; }
                    *(float2*)&Ob[off] = v;
                    if (Cb) *(uint32_t*)&Cb[off] = pack_h2(v.x, v.y);
                }
            }
    }
}

// ---------------- depthwise 3x3 qkv: vectorized 16-row tiles --------------------
__global__ __launch_bounds__(256) void dw_qkv_kernel(const __half* __restrict__ in,
                                                     const float* __restrict__ w9,
                                                     __half* __restrict__ out) {
    __shared__ __half st[18][136];
    __shared__ float red[256];
    int c = blockIdx.y, b = blockIdx.z;
    long long base = ((long long)b * 576 + c) * HW;
    const __half* ib = in + base;
    int y0 = blockIdx.x * 16;
    int tid = threadIdx.x;
    float w[9];
#pragma unroll
    for (int i = 0; i < 9; i++) w[i] = w9[c * 9 + i];

    for (int id = tid; id < 288; id += 256) {
        int r = id >> 4, c8 = (id & 15) * 8;
        int gy = y0 - 1 + r;
        uint4 v = make_uint4(0u, 0u, 0u, 0u);
        if ((unsigned)gy < IMG_W) v = *(const uint4*)&ib[gy * IMG_W + c8];
        *(uint4*)&st[r][c8] = v;
    }
    __syncthreads();

    int r = tid >> 4, x0 = (tid & 15) * 8;
    float o[8] = {};
#pragma unroll
    for (int ky = 0; ky < 3; ky++) {
        float t[10];
#pragma unroll
        for (int i = 0; i < 10; i++) {
            int xx = x0 - 1 + i;
            t[i] = ((unsigned)xx < IMG_W) ? __half2float(st[r + ky][xx]) : 0.f;
        }
        float w0 = w[ky * 3], w1 = w[ky * 3 + 1], w2 = w[ky * 3 + 2];
#pragma unroll
        for (int j = 0; j < 8; j++)
            o[j] += w0 * t[j] + w1 * t[j + 1] + w2 * t[j + 2];
    }
    uint4 pv;
    uint32_t* pp = (uint32_t*)&pv;
#pragma unroll
    for (int i = 0; i < 4; i++) pp[i] = pack_h2(o[2 * i], o[2 * i + 1]);
    *(uint4*)&out[base + (y0 + r) * IMG_W + x0] = pv;

    if (c < 384) {
        float ss = 0.f;
#pragma unroll
        for (int j = 0; j < 8; j++) ss += o[j] * o[j];
        red[tid] = ss;
        __syncthreads();
        for (int stp = 128; stp; stp >>= 1) {
            if (tid < stp) red[tid] += red[tid + stp];
            __syncthreads();
        }
        if (tid == 0)
            g_rnpart[(long long)blockIdx.x * (BATCH * 384) + b * 384 + c] = red[0];
    }
}

// ---------------- split-K partial Q.K^T via tensor cores ------------------------
__global__ __launch_bounds__(256) void attn_part_kernel() {
    __shared__ __align__(16) __half Qs[48][72];
    __shared__ __align__(16) __half Ks[48][72];
    int chunk = blockIdx.x;
    int bh = blockIdx.y;
    int b = bh >> 2, h = bh & 3;
    const __half* qb = g_S1h + ((long long)b * 576 + h * DHEAD) * HW;
    const __half* kb = g_S1h + ((long long)b * 576 + DIM + h * DHEAD) * HW;
    int tid = threadIdx.x, lane = tid & 31, w = tid >> 5;
    int mt = w >> 1, nh = w & 1;
    int ra = lane >> 2, ca = lane & 3;
    long long nbase = (long long)chunk * 1024;

    float acc[3][4] = {};

    for (int sl = 0; sl < 16; sl++) {
        long long nb = nbase + sl * 64;
#pragma unroll
        for (int i = 0; i < 3; i++) {
            int id = tid + i * 256;
            int r = id >> 3;
            int c8 = (id & 7) * 8;
            if (r < 48)
                cpa16(sm_addr(&Qs[r][c8]), &qb[(long long)r * HW + nb + c8]);
            else
                cpa16(sm_addr(&Ks[r - 48][c8]), &kb[(long long)(r - 48) * HW + nb + c8]);
        }
        cpa_commit();
        cpa_wait<0>();
        __syncthreads();
        if (w < 6) {
#pragma unroll
            for (int kp = 0; kp < 4; kp++) {
                uint32_t afr[4], bfr[3][2];
                ldsm_x4(afr, sm_addr(&Qs[mt * 16 + (lane & 15)][kp * 16 + (lane >> 4) * 8]));
#pragma unroll
                for (int tn = 0; tn < 3; tn++)
                    ldsm_x2(bfr[tn], sm_addr(&Ks[nh * 24 + tn * 8 + (lane & 7)]
                                                [kp * 16 + ((lane >> 3) & 1) * 8]));
#pragma unroll
                for (int tn = 0; tn < 3; tn++)
                    mma_f32acc(acc[tn], afr, bfr[tn]);
            }
        }
        __syncthreads();
    }
    if (w < 6) {
        float* P = g_Apart + ((long long)bh * 16 + chunk) * (DHEAD * DHEAD);
#pragma unroll
        for (int tn = 0; tn < 3; tn++) {
            int d0 = nh * 24 + tn * 8 + 2 * ca;
            int c0 = mt * 16 + ra;
            *(float2*)&P[c0 * DHEAD + d0] = make_float2(acc[tn][0], acc[tn][1]);
            *(float2*)&P[(c0 + 8) * DHEAD + d0] = make_float2(acc[tn][2], acc[tn][3]);
        }
    }
}

// ---------------- reduce partials + rownorms, scale, softmax --------------------
__global__ __launch_bounds__(256) void attn_finish_kernel(const float* __restrict__ temp) {
    int bh = blockIdx.x;
    int b = bh >> 2, h = bh & 3;
    __shared__ float sA[DHEAD * DHEAD];
    __shared__ float srn_q[DHEAD], srn_k[DHEAD];
    int tid = threadIdx.x;
    if (tid < 96) {
        int i = tid;
        int isK = (i >= DHEAD);
        int cc = i - isK * DHEAD;
        int row = b * 384 + isK * DIM + h * DHEAD + cc;
        float s = 0.f;
#pragma unroll
        for (int p = 0; p < NPART; p++) s += g_rnpart[(long long)p * (BATCH * 384) + row];
        float v = 1.f / fmaxf(sqrtf(s), 1e-12f);
        if (isK) srn_k[cc] = v; else srn_q[cc] = v;
    }
    __syncthreads();
    for (int i = tid; i < DHEAD * DHEAD; i += 256) {
        float s = 0.f;
        for (int p = 0; p < 16; p++)
            s += g_Apart[((long long)bh * 16 + p) * (DHEAD * DHEAD) + i];
        int c = i / DHEAD, d = i % DHEAD;
        sA[i] = s * srn_q[c] * srn_k[d] * temp[h];
    }
    __syncthreads();
    if (tid < DHEAD) {
        float mx = -1e30f;
        for (int d = 0; d < DHEAD; d++) mx = fmaxf(mx, sA[tid * DHEAD + d]);
        float sum = 0.f;
        for (int d = 0; d < DHEAD; d++) sum += __expf(sA[tid * DHEAD + d] - mx);
        float inv = 1.f / sum;
        for (int d = 0; d < DHEAD; d++)
            g_A[bh * DHEAD * DHEAD + tid * DHEAD + d] =
                __expf(sA[tid * DHEAD + d] - mx) * inv;
    }
}

// ---------------- out = A @ V via tensor cores ----------------------------------
__global__ __launch_bounds__(256) void av_kernel() {
    __shared__ __align__(16) __half Ab[48][56];
    __shared__ __align__(16) __half Vs[48][264];
    int bh = blockIdx.y;
    int b = bh >> 2, h = bh & 3;
    int tid = threadIdx.x, lane = tid & 31, wn = tid >> 5;
    int ra = lane >> 2, ca = lane & 3;
    int n0 = blockIdx.x * 256;

    for (int i = tid; i < DHEAD * DHEAD; i += 256)
        Ab[i / DHEAD][i % DHEAD] = __float2half(g_A[bh * DHEAD * DHEAD + i]);

    const __half* vb = g_S1h + ((long long)b * 576 + 2 * DIM + h * DHEAD) * HW;
#pragma unroll
    for (int i = 0; i < 6; i++) {
        int id = tid + i * 256;
        int d = id >> 5, c8 = (id & 31) * 8;
        cpa16(sm_addr(&Vs[d][c8]), &vb[(long long)d * HW + n0 + c8]);
    }
    cpa_commit();
    cpa_wait<0>();
    __syncthreads();

    float acc[3][4][4];
#pragma unroll
    for (int i = 0; i < 3; i++)
#pragma unroll
        for (int j = 0; j < 4; j++)
#pragma unroll
            for (int q = 0; q < 4; q++) acc[i][j][q] = 0.f;

#pragma unroll
    for (int ks = 0; ks < 3; ks++) {
        uint32_t afr[3][4], bfr[4][2];
#pragma unroll
        for (int mt = 0; mt < 3; mt++)
            ldsm_x4(afr[mt], sm_addr(&Ab[mt * 16 + (lane & 15)][ks * 16 + (lane >> 4) * 8]));
#pragma unroll
        for (int tnp = 0; tnp < 2; tnp++) {
            uint32_t t4[4];
            ldsm_x4t(t4, sm_addr(&Vs[ks * 16 + (lane & 15)]
                                    [wn * 32 + tnp * 16 + (lane >> 4) * 8]));
            bfr[2 * tnp][0] = t4[0]; bfr[2 * tnp][1] = t4[1];
            bfr[2 * tnp + 1][0] = t4[2]; bfr[2 * tnp + 1][1] = t4[3];
        }
#pragma unroll
        for (int mt = 0; mt < 3; mt++)
#pragma unroll
            for (int tn = 0; tn < 4; tn++)
                mma_f32acc(acc[mt][tn], afr[mt], bfr[tn]);
    }

    __half* ob = g_S2h + ((long long)b * DIM + h * DHEAD) * HW;
#pragma unroll
    for (int mt = 0; mt < 3; mt++)
#pragma unroll
        for (int tn = 0; tn < 4; tn++) {
            int col = n0 + wn * 32 + tn * 8 + 2 * ca;
            int c0 = mt * 16 + ra;
            *(uint32_t*)&ob[(long long)c0 * HW + col] =
                pack_h2(acc[mt][tn][0], acc[mt][tn][1]);
            *(uint32_t*)&ob[(long long)(c0 + 8) * HW + col] =
                pack_h2(acc[mt][tn][2], acc[mt][tn][3]);
        }
}

// ---------------- fused GDFN dw3x3 + GELU gate: vectorized 16-row tiles ---------
__global__ __launch_bounds__(256) void dw_gate_kernel(const __half* __restrict__ in,
                                                      const float* __restrict__ w9,
                                                      __half* __restrict__ out) {
    __shared__ __half st1[18][136], st2[18][136];
    int c = blockIdx.y, b = blockIdx.z;
    int y0 = blockIdx.x * 16;
    int tid = threadIdx.x;
    int r = tid >> 4, x0 = (tid & 15) * 8;
    long long obase = ((long long)b * 512 + c) * HW;

    if (c >= HIDDEN) {
        uint4 z = make_uint4(0u, 0u, 0u, 0u);
        *(uint4*)&out[obase + (y0 + r) * IMG_W + x0] = z;
        return;
    }
    long long base1 = ((long long)b * 1020 + c) * HW;
    long long base2 = ((long long)b * 1020 + HIDDEN + c) * HW;
    float w1[9], w2[9];
#pragma unroll
    for (int i = 0; i < 9; i++) { w1[i] = w9[c * 9 + i]; w2[i] = w9[(HIDDEN + c) * 9 + i]; }

    for (int id = tid; id < 288; id += 256) {
        int rr = id >> 4, c8 = (id & 15) * 8;
        int gy = y0 - 1 + rr;
        uint4 v1 = make_uint4(0u, 0u, 0u, 0u), v2 = v1;
        if ((unsigned)gy < IMG_W) {
            v1 = *(const uint4*)&in[base1 + gy * IMG_W + c8];
            v2 = *(const uint4*)&in[base2 + gy * IMG_W + c8];
        }
        *(uint4*)&st1[rr][c8] = v1;
        *(uint4*)&st2[rr][c8] = v2;
    }
    __syncthreads();

    float o1[8] = {}, o2[8] = {};
#pragma unroll
    for (int ky = 0; ky < 3; ky++) {
        float t1[10], t2[10];
#pragma unroll
        for (int i = 0; i < 10; i++) {
            int xx = x0 - 1 + i;
            bool ok = (unsigned)xx < IMG_W;
            t1[i] = ok ? __half2float(st1[r + ky][xx]) : 0.f;
            t2[i] = ok ? __half2float(st2[r + ky][xx]) : 0.f;
        }
        float a0 = w1[ky * 3], a1 = w1[ky * 3 + 1], a2 = w1[ky * 3 + 2];
        float b0 = w2[ky * 3], b1 = w2[ky * 3 + 1], b2 = w2[ky * 3 + 2];
#pragma unroll
        for (int j = 0; j < 8; j++) {
            o1[j] += a0 * t1[j] + a1 * t1[j + 1] + a2 * t1[j + 2];
            o2[j] += b0 * t2[j] + b1 * t2[j + 1] + b2 * t2[j + 2];
        }
    }
    uint4 pv;
    uint32_t* pp = (uint32_t*)&pv;
#pragma unroll
    for (int i = 0; i < 4; i++) {
        float g0 = 0.5f * o1[2 * i] * (1.f + erff(o1[2 * i] * 0.70710678118654752f));
        float g1 = 0.5f * o1[2 * i + 1] * (1.f + erff(o1[2 * i + 1] * 0.70710678118654752f));
        pp[i] = pack_h2(g0 * o2[2 * i], g1 * o2[2 * i + 1]);
    }
    *(uint4*)&out[obase + (y0 + r) * IMG_W + x0] = pv;
}

// =============================================================================
extern "C" void kernel_launch(void* const* d_in, const int* in_sizes, int n_in,
                              void* d_out, int out_size) {
    const float* x     = (const float*)d_in[0];
    const float* n1w   = (const float*)d_in[1];
    const float* qkvw  = (const float*)d_in[2];
    const float* qkvdw = (const float*)d_in[3];
    const float* temp  = (const float*)d_in[4];
    const float* projw = (const float*)d_in[5];
    const float* n2w   = (const float*)d_in[6];
    const float* pinw  = (const float*)d_in[7];
    const float* dww   = (const float*)d_in[8];
    const float* poutw = (const float*)d_in[9];
    float* out = (float*)d_out;

    __half *S0h, *S1h, *S2h, *Wqkv, *Wproj, *Wpin, *Wpout;
    cudaGetSymbolAddress((void**)&S0h, g_S0h);
    cudaGetSymbolAddress((void**)&S1h, g_S1h);
    cudaGetSymbolAddress((void**)&S2h, g_S2h);
    cudaGetSymbolAddress((void**)&Wqkv, g_Wqkv);
    cudaGetSymbolAddress((void**)&Wproj, g_Wproj);
    cudaGetSymbolAddress((void**)&Wpin, g_Wpin);
    cudaGetSymbolAddress((void**)&Wpout, g_Wpout);

    dim3 pxGrid(HW / 256, BATCH);

    // ---- MDTA branch (qkv GEMM kept in ncu's capture slot: 4th launch) ----
    wconv_kernel<<<(576 * 192 + 255) / 256, 256>>>(qkvw, Wqkv, 576, 192, 576, 192);
    wconv_kernel<<<(192 * 192 + 255) / 256, 256>>>(projw, Wproj, 192, 192, 192, 192);
    ln_apply_kernel<<<pxGrid, 256>>>(x, n1w, S2h);

    // qkv 1x1: 576x192 -> fp16
    gemm_fp16<<<dim3(HW / 256, 9, BATCH), 128>>>(
        Wqkv, S2h, S0h, nullptr, nullptr,
        576, 192, (long long)DIM * HW, (long long)576 * HW, 1, 0);

    dw_qkv_kernel<<<dim3(NPART, 576, BATCH), 256>>>(S0h, qkvdw, S1h);
    attn_part_kernel<<<dim3(16, 16), 256>>>();
    attn_finish_kernel<<<16, 256>>>(temp);
    av_kernel<<<dim3(HW / 256, 16), 256>>>();

    // proj 1x1 (192x192): fp16 -> fp32 + residual(x); also fp16 copy into S0h
    gemm_fp16<<<dim3(HW / 256, 3, BATCH), 128>>>(
        Wproj, S2h, out, x, S0h,
        192, 192, (long long)DIM * HW, (long long)DIM * HW, 0, 1);

    // ---- GDFN branch ----
    wconv_kernel<<<(1024 * 192 + 255) / 256, 256>>>(pinw, Wpin, 1020, 192, 1024, 192);
    wconv_kernel<<<(192 * 512 + 255) / 256, 256>>>(poutw, Wpout, 192, 510, 192, 512);
    // ln2 reads the fp16 copy (note: copy laid out with obs = DIM*HW)
    ln_apply_h_kernel<<<pxGrid, 256>>>(S0h, n2w, S2h);

    // pin 1x1 (1020x192 padded 1024): fp16 -> fp16
    gemm_fp16<<<dim3(HW / 256, 16, BATCH), 128>>>(
        Wpin, S2h, S0h, nullptr, nullptr,
        1020, 192, (long long)DIM * HW, (long long)1020 * HW, 1, 0);

    dw_gate_kernel<<<dim3(NPART, 512, BATCH), 256>>>(S0h, dww, S1h);

    // pout 1x1 (192x512 padded K): fp16 -> fp32 + residual(d_out)
    gemm_fp16<<<dim3(HW / 256, 3, BATCH), 128>>>(
        Wpout, S1h, out, out, nullptr,
        192, 512, (long long)512 * HW, (long long)DIM * HW, 0, 1);
}